// round 12
// baseline (speedup 1.0000x reference)
#include <cuda_runtime.h>
#include <math.h>

#define Nn 2000
#define Ee 20000
#define Cc 16
#define Bb 128
#define EPS 1e-5f
#define CHUNK 128

typedef unsigned long long u64;

__device__ __forceinline__ bool is_func(int n) { return n >= 200 && n < 1800; }

// ---- packed f32x2 helpers ---------------------------------------------------
__device__ __forceinline__ u64 fma2(u64 a, u64 b, u64 c) {
    u64 d;
    asm("fma.rn.f32x2 %0, %1, %2, %3;" : "=l"(d) : "l"(a), "l"(b), "l"(c));
    return d;
}
__device__ __forceinline__ u64 splat2(float x) {
    u64 d;
    unsigned r = __float_as_uint(x);
    asm("mov.b64 %0, {%1, %1};" : "=l"(d) : "r"(r));
    return d;
}
__device__ __forceinline__ void unpack2(u64 v, float& lo, float& hi) {
    unsigned a, b;
    asm("mov.b64 {%0, %1}, %2;" : "=r"(a), "=r"(b) : "l"(v));
    lo = __uint_as_float(a); hi = __uint_as_float(b);
}
__device__ __forceinline__ u64 pack2(float lo, float hi) {
    u64 d;
    unsigned a = __float_as_uint(lo), b = __float_as_uint(hi);
    asm("mov.b64 %0, {%1, %2};" : "=l"(d) : "r"(a), "r"(b));
    return d;
}

// ---------------- device scratch (allocation-free) --------------------------
__device__ float g_xT[Nn * Bb];
__device__ float g_xeA[Ee * Bb];
__device__ float g_xeB[Ee * Bb];
__device__ float g_pw1[Ee * Cc];
__device__ float g_pw3m[Ee * Cc];
__device__ float g_pb3[Ee];
__device__ int   g_psrcd[Ee];
__device__ int   g_rowidx[Ee];
__device__ float g_osum[200 * Bb];
__device__ int   g_cntD[Nn], g_cntS[Nn];       // zero at load; re-zeroed by k_out
__device__ int   g_cntO[Nn], g_cntM[Nn];
__device__ int   g_rsD[Nn + 1], g_rsS[Nn + 1];
__device__ int   g_curD[Nn];
__device__ int   g_cur0[Nn], g_cur1[Nn], g_cur2[Nn];
__device__ int   g_sb1[Nn];    // rsS + O   (scatter end, last layer)
__device__ int   g_sb2[Nn];    // rsS + O+M (scatter end, layers 0-2 / const)
__device__ int   g_order[1600];  // func nodes, heaviest-first
__device__ int   g_wt[1600];

// ---------------- preprocessing ---------------------------------------------
__global__ void __launch_bounds__(256) k_init(
        const float* __restrict__ x,
        const int* __restrict__ src, const int* __restrict__ dst) {
    __shared__ float tile[32][33];
    int bx = blockIdx.x, by = blockIdx.y;
    int tx = threadIdx.x & 31, ty = threadIdx.x >> 5;
    int n0 = bx * 32, b0 = by * 32;
#pragma unroll
    for (int k = 0; k < 32; k += 8) {
        int n = n0 + tx, b = b0 + ty + k;
        if (n < Nn) tile[ty + k][tx] = x[b * Nn + n];
    }
    __syncthreads();
#pragma unroll
    for (int k = 0; k < 32; k += 8) {
        int n = n0 + ty + k, b = b0 + tx;
        if (n < Nn) g_xT[n * Bb + b] = tile[tx][ty + k];
    }
    int t = (blockIdx.y * gridDim.x + blockIdx.x) * 256 + threadIdx.x;
    if (t < Ee) {
        int d = dst[t], s = src[t];
        atomicAdd(&g_cntD[d], 1);
        atomicAdd(&g_cntS[s], 1);
        if (d >= 1800)      atomicAdd(&g_cntO[s], 1);
        else if (d >= 200)  atomicAdd(&g_cntM[s], 1);
    }
}

__global__ void __launch_bounds__(1024) k_scan() {
    __shared__ int sh[2048];
    const int* cnt = blockIdx.x ? g_cntS : g_cntD;
    int* rs = blockIdx.x ? g_rsS : g_rsD;
    int t = threadIdx.x;
    sh[t]        = (t < Nn) ? cnt[t] : 0;
    sh[t + 1024] = (t + 1024 < Nn) ? cnt[t + 1024] : 0;
    __syncthreads();
    for (int off = 1; off < 2048; off <<= 1) {
        int v0 = (t >= off) ? sh[t - off] : 0;
        int v1 = (t + 1024 >= off) ? sh[t + 1024 - off] : 0;
        __syncthreads();
        sh[t] += v0;
        sh[t + 1024] += v1;
        __syncthreads();
    }
#pragma unroll
    for (int h = 0; h < 2; h++) {
        int i = t + h * 1024;
        if (i < Nn) {
            int v = (i == 0) ? 0 : sh[i - 1];
            rs[i] = v;
            if (blockIdx.x == 0) {
                g_curD[i] = v;
            } else {
                int o = g_cntO[i], m = g_cntM[i];
                g_cur0[i] = v;
                g_cur1[i] = v + o;
                g_cur2[i] = v + o + m;
                g_sb1[i]  = v + o;
                g_sb2[i]  = v + o + m;
            }
        }
    }
    if (t == 0) rs[Nn] = sh[Nn - 1];
}

// heavy-first task order: counting sort by (inDeg + live outDeg), descending
__global__ void __launch_bounds__(1024) k_sort() {
    __shared__ int hist[64], off[64];
    int t = threadIdx.x;
    if (t < 64) hist[t] = 0;
    __syncthreads();
    for (int i = t; i < 1600; i += 1024) {
        int n = 200 + i;
        int w = (g_rsD[n + 1] - g_rsD[n]) + (g_sb2[n] - g_rsS[n]);
        w = min(w, 63);
        g_wt[i] = w;
        atomicAdd(&hist[w], 1);
    }
    __syncthreads();
    if (t < 64) {
        int s = 0;
        for (int w = 63; w > t; w--) s += hist[w];
        off[t] = s;
    }
    __syncthreads();
    if (t < 64) hist[t] = off[t];   // reuse as cursors
    __syncthreads();
    for (int i = t; i < 1600; i += 1024) {
        int pos = atomicAdd(&hist[g_wt[i]], 1);
        g_order[pos] = 200 + i;
    }
}

__global__ void __launch_bounds__(256) k_build(
        const float* __restrict__ w1, const float* __restrict__ w3,
        const float* __restrict__ b3,
        const int* __restrict__ src, const int* __restrict__ dst) {
    __shared__ int sE[256], sPd[256], sPs[256];
    __shared__ float sFm[256];
    int e = blockIdx.x * 256 + threadIdx.x;
    int nEdge = min(256, Ee - blockIdx.x * 256);
    if (e < Ee) {
        int s = src[e], d = dst[e];
        int pd = atomicAdd(&g_curD[d], 1);
        int* cur = (d >= 1800) ? g_cur0 : ((d >= 200) ? g_cur1 : g_cur2);
        int ps = atomicAdd(&cur[s], 1);
        g_psrcd[pd]  = s * Bb;
        g_rowidx[pd] = ps * Bb;
        g_pb3[ps]    = b3[e];
        sE[threadIdx.x]  = e;
        sPd[threadIdx.x] = pd;
        sPs[threadIdx.x] = ps;
        sFm[threadIdx.x] = is_func(s) ? 1.0f : 0.0f;
    }
    __syncthreads();
    for (int i = threadIdx.x; i < nEdge * 16; i += 256) {
        int j = i >> 4, c = i & 15;
        int e2 = sE[j];
        g_pw1[sPd[j] * 16 + c]  = w1[e2 * 16 + c];
        g_pw3m[sPs[j] * 16 + c] = w3[e2 * 16 + c] * sFm[j];
    }
}

// ---------------- shared layout ----------------------------------------------
struct SmemT {
    union {
        float4 stage4[CHUNK * 4];
        float  stage[CHUNK * 16];
        float  shh[128][17];
    };
    float4 shw4[16][4];
    float  shs[8][16], shs2[8][16];
    float  shscale[16], shshift[16];
    int    sidx[CHUNK];
    float  sb3[CHUNK];
};

// ---------------- BN + ELU ---------------------------------------------------
__device__ __forceinline__ void bn_elu(float* acc, int n, int b,
                                       const float* __restrict__ gamma,
                                       const float* __restrict__ beta,
                                       SmemT* sm) {
    __syncthreads();
#pragma unroll
    for (int c = 0; c < 16; c++) sm->shh[b][c] = acc[c];
    __syncthreads();
    int c0 = b & 15, gg = b >> 4;
    float s = 0.f, s2 = 0.f;
#pragma unroll
    for (int k = 0; k < 16; k++) {
        float v = sm->shh[gg + 8 * k][c0];
        s += v; s2 += v * v;
    }
    sm->shs[gg][c0] = s;
    sm->shs2[gg][c0] = s2;
    __syncthreads();
    if (b < 16) {
        float S = 0.f, S2 = 0.f;
#pragma unroll
        for (int g = 0; g < 8; g++) { S += sm->shs[g][b]; S2 += sm->shs2[g][b]; }
        float m   = S * (1.0f / 128.0f);
        float var = S2 * (1.0f / 128.0f) - m * m;
        float rsg = rsqrtf(var + EPS);
        float sc  = gamma[n * 16 + b] * rsg;
        sm->shscale[b] = sc;
        sm->shshift[b] = beta[n * 16 + b] - m * sc;
    }
    __syncthreads();
#pragma unroll
    for (int c = 0; c < 16; c++) {
        float v = acc[c] * sm->shscale[c] + sm->shshift[c];
        acc[c] = v > 0.f ? v : (__expf(v) - 1.0f);
    }
}

// ---------------- fused per-layer kernel -------------------------------------
__global__ void __launch_bounds__(128, 12) k_layer(
    const float* __restrict__ xe_rows, int use_psrc,
    float* __restrict__ xe_out, const int* __restrict__ qend,
    const float* __restrict__ b1, const float* __restrict__ w2,
    const float* __restrict__ b2,
    const float* __restrict__ g1, const float* __restrict__ be1,
    const float* __restrict__ g2, const float* __restrict__ be2) {
    __shared__ SmemT sm;
    int t = blockIdx.x;
    int b = threadIdx.x;

    if (t >= 1600) {   // const-edge writer (layer-0 grid only)
        int i = t - 1600;
        int n = (i < 200) ? i : (1600 + i);
        float xb = g_xT[n * Bb + b];
        int qs = g_rsS[n], qe = g_sb2[n];
        for (int q = qs; q < qe; q++) {
            float v = xb + g_pb3[q];
            g_xeA[q * Bb + b] = v;
            g_xeB[q * Bb + b] = v;
        }
        return;
    }

    int n = g_order[t];                       // heavy-first schedule
    const int* rowix = use_psrc ? g_psrcd : g_rowidx;

    // prefetch w2 row early; visibility covered by first gather-stage barrier
    {
        const float4* w2p = (const float4*)(w2 + n * 256);
        for (int i = b; i < 64; i += 128) sm.shw4[i >> 2][i & 3] = w2p[i];
    }

    u64 acc2[8];
    {
        const ulonglong2* bp = (const ulonglong2*)(b1 + n * 16);
#pragma unroll
        for (int k = 0; k < 4; k++) {
            ulonglong2 q = bp[k];
            acc2[2 * k] = q.x; acc2[2 * k + 1] = q.y;
        }
    }

    // ---- gather ----
    int rs = g_rsD[n], re = g_rsD[n + 1];
    for (int cbase = rs; cbase < re; cbase += CHUNK) {
        int cnt = min(CHUNK, re - cbase);
        __syncthreads();
        for (int i = b; i < cnt * 16; i += 128) sm.stage[i] = g_pw1[cbase * 16 + i];
        if (b < cnt) sm.sidx[b] = rowix[cbase + b];
        __syncthreads();
        for (int jb = 0; jb < cnt; jb += 8) {
            float xv[8];
#pragma unroll
            for (int j = 0; j < 8; j++) {
                int jj = jb + j;
                xv[j] = (jj < cnt) ? xe_rows[sm.sidx[jj] + b] : 0.0f;
            }
#pragma unroll
            for (int j = 0; j < 8; j++) {
                int jj = jb + j;
                if (jj < cnt) {
                    u64 xv2 = splat2(xv[j]);
                    const ulonglong2* wp = (const ulonglong2*)&sm.stage[jj * 16];
                    ulonglong2 q0 = wp[0], q1 = wp[1], q2 = wp[2], q3 = wp[3];
                    acc2[0] = fma2(q0.x, xv2, acc2[0]);
                    acc2[1] = fma2(q0.y, xv2, acc2[1]);
                    acc2[2] = fma2(q1.x, xv2, acc2[2]);
                    acc2[3] = fma2(q1.y, xv2, acc2[3]);
                    acc2[4] = fma2(q2.x, xv2, acc2[4]);
                    acc2[5] = fma2(q2.y, xv2, acc2[5]);
                    acc2[6] = fma2(q3.x, xv2, acc2[6]);
                    acc2[7] = fma2(q3.y, xv2, acc2[7]);
                }
            }
        }
    }

    float acc[16];
#pragma unroll
    for (int k = 0; k < 8; k++) unpack2(acc2[k], acc[2 * k], acc[2 * k + 1]);

    bn_elu(acc, n, b, g1, be1, &sm);

    // ---- 16x16 matmul: thread reads/writes only its own shh row => no syncs
    // (shw4 was prefetched at kernel start; its stores are ordered before the
    //  gather-stage barriers, hence visible here)
#pragma unroll
    for (int c = 0; c < 16; c++) sm.shh[b][c] = acc[c];

    u64 out2[8];
    {
        const ulonglong2* bp = (const ulonglong2*)(b2 + n * 16);
#pragma unroll
        for (int k = 0; k < 4; k++) {
            ulonglong2 q = bp[k];
            out2[2 * k] = q.x; out2[2 * k + 1] = q.y;
        }
    }
#pragma unroll
    for (int c = 0; c < 16; c++) {
        u64 v2 = splat2(sm.shh[b][c]);
        const ulonglong2* wp = (const ulonglong2*)&sm.shw4[c][0];
        ulonglong2 q0 = wp[0], q1 = wp[1], q2 = wp[2], q3 = wp[3];
        out2[0] = fma2(q0.x, v2, out2[0]);
        out2[1] = fma2(q0.y, v2, out2[1]);
        out2[2] = fma2(q1.x, v2, out2[2]);
        out2[3] = fma2(q1.y, v2, out2[3]);
        out2[4] = fma2(q2.x, v2, out2[4]);
        out2[5] = fma2(q2.y, v2, out2[5]);
        out2[6] = fma2(q3.x, v2, out2[6]);
        out2[7] = fma2(q3.y, v2, out2[7]);
    }

    float out[16];
#pragma unroll
    for (int k = 0; k < 8; k++) unpack2(out2[k], out[2 * k], out[2 * k + 1]);

    bn_elu(out, n, b, g2, be2, &sm);

#pragma unroll
    for (int k = 0; k < 8; k++) out2[k] = pack2(out[2 * k], out[2 * k + 1]);

    // ---- scatter (live edges only) ----
    float xb = g_xT[n * Bb + b];
    int qs = g_rsS[n], qe = qend[n];
    for (int cbase = qs; cbase < qe; cbase += CHUNK) {
        int cnt = min(CHUNK, qe - cbase);
        __syncthreads();
        for (int i = b; i < cnt * 16; i += 128) sm.stage[i] = g_pw3m[cbase * 16 + i];
        if (b < cnt) sm.sb3[b] = g_pb3[cbase + b];
        __syncthreads();
        for (int j = 0; j < cnt; j++) {
            const ulonglong2* wq = (const ulonglong2*)&sm.stage[j * 16];
            ulonglong2 q0 = wq[0], q1 = wq[1], q2 = wq[2], q3 = wq[3];
            u64 s2 = 0ULL;
            s2 = fma2(q0.x, out2[0], s2);
            s2 = fma2(q0.y, out2[1], s2);
            s2 = fma2(q1.x, out2[2], s2);
            s2 = fma2(q1.y, out2[3], s2);
            s2 = fma2(q2.x, out2[4], s2);
            s2 = fma2(q2.y, out2[5], s2);
            s2 = fma2(q3.x, out2[6], s2);
            s2 = fma2(q3.y, out2[7], s2);
            float lo, hi;
            unpack2(s2, lo, hi);
            xe_out[(cbase + j) * Bb + b] = xb + sm.sb3[j] + (lo + hi);
        }
    }
}

// ---------------- final: compact sums, then coalesced output -----------------
__global__ void __launch_bounds__(128) k_sum(const float* __restrict__ xe) {
    int n = 1800 + blockIdx.x;
    int b = threadIdx.x;
    float s = 0.f;
    int rs = g_rsD[n], re = g_rsD[n + 1];
    for (int p = rs; p < re; p++) s += xe[g_rowidx[p] + b];
    g_osum[blockIdx.x * Bb + b] = s;
}

__global__ void __launch_bounds__(256) k_out(float* __restrict__ out) {
    int t = blockIdx.x * 256 + threadIdx.x;
    if (t < Bb * Nn) {
        int n = t % Nn;
        int b = t / Nn;
        out[t] = (n >= 1800) ? g_osum[(n - 1800) * Bb + b] : 0.0f;
    }
    if (t < Nn) { g_cntD[t] = 0; g_cntS[t] = 0; g_cntO[t] = 0; g_cntM[t] = 0; }
}

// ---------------- launch ----------------------------------------------------
extern "C" void kernel_launch(void* const* d_in, const int* in_sizes, int n_in,
                              void* d_out, int out_size) {
    const float* x   = (const float*)d_in[0];
    const float* w1  = (const float*)d_in[1];
    const float* b1  = (const float*)d_in[2];
    const float* w2  = (const float*)d_in[3];
    const float* b2  = (const float*)d_in[4];
    const float* w3  = (const float*)d_in[5];
    const float* b3  = (const float*)d_in[6];
    const float* g1  = (const float*)d_in[7];
    const float* be1 = (const float*)d_in[8];
    const float* g2  = (const float*)d_in[9];
    const float* be2 = (const float*)d_in[10];
    const int*   ei  = (const int*)d_in[11];
    float* out = (float*)d_out;

    const int* src = ei;
    const int* dst = ei + Ee;

    static float* xeA = nullptr;
    static float* xeB = nullptr;
    static float* xT  = nullptr;
    static int*   sb1 = nullptr;
    static int*   sb2 = nullptr;
    if (!xeA) {
        cudaGetSymbolAddress((void**)&xeA, g_xeA);
        cudaGetSymbolAddress((void**)&xeB, g_xeB);
        cudaGetSymbolAddress((void**)&xT,  g_xT);
        cudaGetSymbolAddress((void**)&sb1, g_sb1);
        cudaGetSymbolAddress((void**)&sb2, g_sb2);
        cudaFuncSetAttribute(k_layer,
            cudaFuncAttributePreferredSharedMemoryCarveout, 100);
    }

    dim3 gInit(63, 4);
    k_init<<<gInit, 256>>>(x, src, dst);
    k_scan<<<2, 1024>>>();
    k_sort<<<1, 1024>>>();
    k_build<<<(Ee + 255) / 256, 256>>>(w1, w3, b3, src, dst);

    k_layer<<<2000, 128>>>(xT,  1, xeA, sb2, b1, w2, b2, g1, be1, g2, be2);
    k_layer<<<1600, 128>>>(xeA, 0, xeB, sb2, b1, w2, b2, g1, be1, g2, be2);
    k_layer<<<1600, 128>>>(xeB, 0, xeA, sb2, b1, w2, b2, g1, be1, g2, be2);
    k_layer<<<1600, 128>>>(xeA, 0, xeB, sb1, b1, w2, b2, g1, be1, g2, be2);

    k_sum<<<200, 128>>>(xeB);
    k_out<<<(Bb * Nn + 255) / 256, 256>>>(out);
}

// round 13
// speedup vs baseline: 1.0465x; 1.0465x over previous
#include <cuda_runtime.h>
#include <math.h>

#define Nn 2000
#define Ee 20000
#define Bb 128
#define EPS 1e-5f
#define CH 64          // edges staged per chunk
#define NLB 800        // layer blocks (2 nodes per block)

typedef unsigned long long u64;

__device__ __forceinline__ bool is_func(int n) { return n >= 200 && n < 1800; }

// ---- packed f32x2 helpers ---------------------------------------------------
__device__ __forceinline__ u64 fma2(u64 a, u64 b, u64 c) {
    u64 d;
    asm("fma.rn.f32x2 %0, %1, %2, %3;" : "=l"(d) : "l"(a), "l"(b), "l"(c));
    return d;
}
__device__ __forceinline__ u64 splat2(float x) {
    u64 d;
    unsigned r = __float_as_uint(x);
    asm("mov.b64 %0, {%1, %1};" : "=l"(d) : "r"(r));
    return d;
}
__device__ __forceinline__ void unpack2(u64 v, float& lo, float& hi) {
    unsigned a, b;
    asm("mov.b64 {%0, %1}, %2;" : "=r"(a), "=r"(b) : "l"(v));
    lo = __uint_as_float(a); hi = __uint_as_float(b);
}
__device__ __forceinline__ u64 pack2(float lo, float hi) {
    u64 d;
    unsigned a = __float_as_uint(lo), b = __float_as_uint(hi);
    asm("mov.b64 %0, {%1, %2};" : "=l"(d) : "r"(a), "r"(b));
    return d;
}
__device__ __forceinline__ u64 elu2(u64 v) {
    float lo, hi;
    unpack2(v, lo, hi);
    lo = lo > 0.f ? lo : (__expf(lo) - 1.0f);
    hi = hi > 0.f ? hi : (__expf(hi) - 1.0f);
    return pack2(lo, hi);
}

// ---------------- device scratch (allocation-free) --------------------------
__device__ float g_xT[Nn * Bb];
__device__ float g_xeA[Ee * Bb];
__device__ float g_xeB[Ee * Bb];
__device__ float g_pw1[Ee * 16];
__device__ float g_pw3m[Ee * 16];
__device__ float g_pb3[Ee];
__device__ int   g_psrcd[Ee];        // src row offset (*Bb), dst order
__device__ int   g_rowidx[Ee];       // src-CSR row offset (*Bb), dst order
__device__ float g_osum[200 * Bb];
__device__ int   g_cntD[Nn], g_cntS[Nn];   // zero at load; re-zeroed by k_out
__device__ int   g_cntO[Nn], g_cntM[Nn];
__device__ int   g_rsD[Nn + 1], g_rsS[Nn + 1];
__device__ int   g_curD[Nn];
__device__ int   g_cur0[Nn], g_cur1[Nn], g_cur2[Nn];
__device__ int   g_sb1[Nn];    // rsS + O   (scatter end, last layer)
__device__ int   g_sb2[Nn];    // rsS + O+M (scatter end, layers 0-2 / const)

// ---------------- preprocessing ---------------------------------------------
__global__ void __launch_bounds__(256) k_init(
        const float* __restrict__ x,
        const int* __restrict__ src, const int* __restrict__ dst) {
    __shared__ float tile[32][33];
    int bx = blockIdx.x, by = blockIdx.y;
    int tx = threadIdx.x & 31, ty = threadIdx.x >> 5;
    int n0 = bx * 32, b0 = by * 32;
#pragma unroll
    for (int k = 0; k < 32; k += 8) {
        int n = n0 + tx, b = b0 + ty + k;
        if (n < Nn) tile[ty + k][tx] = x[b * Nn + n];
    }
    __syncthreads();
#pragma unroll
    for (int k = 0; k < 32; k += 8) {
        int n = n0 + ty + k, b = b0 + tx;
        if (n < Nn) g_xT[n * Bb + b] = tile[tx][ty + k];
    }
    int t = (blockIdx.y * gridDim.x + blockIdx.x) * 256 + threadIdx.x;
    if (t < Ee) {
        int d = dst[t], s = src[t];
        atomicAdd(&g_cntD[d], 1);
        atomicAdd(&g_cntS[s], 1);
        if (d >= 1800)      atomicAdd(&g_cntO[s], 1);
        else if (d >= 200)  atomicAdd(&g_cntM[s], 1);
    }
}

__global__ void __launch_bounds__(1024) k_scan() {
    __shared__ int sh[2048];
    const int* cnt = blockIdx.x ? g_cntS : g_cntD;
    int* rs = blockIdx.x ? g_rsS : g_rsD;
    int t = threadIdx.x;
    sh[t]        = (t < Nn) ? cnt[t] : 0;
    sh[t + 1024] = (t + 1024 < Nn) ? cnt[t + 1024] : 0;
    __syncthreads();
    for (int off = 1; off < 2048; off <<= 1) {
        int v0 = (t >= off) ? sh[t - off] : 0;
        int v1 = (t + 1024 >= off) ? sh[t + 1024 - off] : 0;
        __syncthreads();
        sh[t] += v0;
        sh[t + 1024] += v1;
        __syncthreads();
    }
#pragma unroll
    for (int h = 0; h < 2; h++) {
        int i = t + h * 1024;
        if (i < Nn) {
            int v = (i == 0) ? 0 : sh[i - 1];
            rs[i] = v;
            if (blockIdx.x == 0) {
                g_curD[i] = v;
            } else {
                int o = g_cntO[i], m = g_cntM[i];
                g_cur0[i] = v;
                g_cur1[i] = v + o;
                g_cur2[i] = v + o + m;
                g_sb1[i]  = v + o;
                g_sb2[i]  = v + o + m;
            }
        }
    }
    if (t == 0) rs[Nn] = sh[Nn - 1];
}

__global__ void __launch_bounds__(256) k_build(
        const float* __restrict__ w1, const float* __restrict__ w3,
        const float* __restrict__ b3,
        const int* __restrict__ src, const int* __restrict__ dst) {
    __shared__ int sE[256], sPd[256], sPs[256];
    __shared__ float sFm[256];
    int e = blockIdx.x * 256 + threadIdx.x;
    int nEdge = min(256, Ee - blockIdx.x * 256);
    if (e < Ee) {
        int s = src[e], d = dst[e];
        int pd = atomicAdd(&g_curD[d], 1);
        int* cur = (d >= 1800) ? g_cur0 : ((d >= 200) ? g_cur1 : g_cur2);
        int ps = atomicAdd(&cur[s], 1);
        g_psrcd[pd]  = s * Bb;
        g_rowidx[pd] = ps * Bb;
        g_pb3[ps]    = b3[e];
        sE[threadIdx.x]  = e;
        sPd[threadIdx.x] = pd;
        sPs[threadIdx.x] = ps;
        sFm[threadIdx.x] = is_func(s) ? 1.0f : 0.0f;
    }
    __syncthreads();
    for (int i = threadIdx.x; i < nEdge * 16; i += 256) {
        int j = i >> 4, c = i & 15;
        int e2 = sE[j];
        g_pw1[sPd[j] * 16 + c]  = w1[e2 * 16 + c];
        g_pw3m[sPs[j] * 16 + c] = w3[e2 * 16 + c] * sFm[j];
    }
}

// ---------------- per-node shared block --------------------------------------
struct __align__(16) NodeSm {
    union {
        float stage[CH * 16];      // 4KB   weight staging (gather/scatter)
        float shh[128][18];        // 9KB   BN transpose + h parking (72B rows)
    };
    float shw[16][16];             // 1KB   w2 tile
    float shs[4][16], shs2[4][16];
    float shscale[16], shshift[16];
    int   sidx[CH];
    float sb3[CH];
};

// ---------------- BN + ELU (64 threads per node, lanes u / u+64) -------------
__device__ __forceinline__ void bn_elu2(u64* a0, u64* a1, int n, int u,
                                        const float* __restrict__ gamma,
                                        const float* __restrict__ beta,
                                        NodeSm* sm) {
    __syncthreads();
#pragma unroll
    for (int k = 0; k < 8; k++) {
        *(u64*)&sm->shh[u][2 * k]      = a0[k];
        *(u64*)&sm->shh[u + 64][2 * k] = a1[k];
    }
    __syncthreads();
    int c0 = u & 15, gg = u >> 4;    // 4 groups x 16 channels
    float s = 0.f, s2 = 0.f;
#pragma unroll
    for (int k = 0; k < 32; k++) {
        float v = sm->shh[gg * 32 + k][c0];
        s += v; s2 += v * v;
    }
    sm->shs[gg][c0] = s;
    sm->shs2[gg][c0] = s2;
    __syncthreads();
    if (u < 16) {
        float S  = sm->shs[0][u] + sm->shs[1][u] + sm->shs[2][u] + sm->shs[3][u];
        float S2 = sm->shs2[0][u] + sm->shs2[1][u] + sm->shs2[2][u] + sm->shs2[3][u];
        float m   = S * (1.0f / 128.0f);
        float var = S2 * (1.0f / 128.0f) - m * m;
        float rsg = rsqrtf(var + EPS);
        float sc  = gamma[n * 16 + u] * rsg;
        sm->shscale[u] = sc;
        sm->shshift[u] = beta[n * 16 + u] - m * sc;
    }
    __syncthreads();
    const ulonglong2* scp = (const ulonglong2*)sm->shscale;
    const ulonglong2* shp = (const ulonglong2*)sm->shshift;
#pragma unroll
    for (int k2 = 0; k2 < 4; k2++) {
        ulonglong2 sc = scp[k2], sh = shp[k2];
        a0[2 * k2]     = elu2(fma2(a0[2 * k2],     sc.x, sh.x));
        a0[2 * k2 + 1] = elu2(fma2(a0[2 * k2 + 1], sc.y, sh.y));
        a1[2 * k2]     = elu2(fma2(a1[2 * k2],     sc.x, sh.x));
        a1[2 * k2 + 1] = elu2(fma2(a1[2 * k2 + 1], sc.y, sh.y));
    }
}

// ---------------- fused per-layer kernel: 2 nodes/block, 64 thr/node --------
__global__ void __launch_bounds__(128, 8) k_layer(
    const float* __restrict__ xe_rows, int use_psrc,
    float* __restrict__ xe_out, const int* __restrict__ qend,
    const float* __restrict__ b1, const float* __restrict__ w2,
    const float* __restrict__ b2,
    const float* __restrict__ g1, const float* __restrict__ be1,
    const float* __restrict__ g2, const float* __restrict__ be2) {
    __shared__ NodeSm smarr[2];
    int t = blockIdx.x;
    int tid = threadIdx.x;
    int slot = tid >> 6, u = tid & 63;
    NodeSm* sm = &smarr[slot];

    if (t >= NLB) {   // const-edge writers (layer-0 grid only), 2 per block
        int i = (t - NLB) * 2 + slot;
        int n = (i < 200) ? i : (1600 + i);
        float xb0 = g_xT[n * Bb + u], xb1 = g_xT[n * Bb + u + 64];
        int qs = g_rsS[n], qe = g_sb2[n];
        for (int q = qs; q < qe; q++) {
            float bb = g_pb3[q];
            g_xeA[q * Bb + u]      = xb0 + bb;
            g_xeA[q * Bb + u + 64] = xb1 + bb;
            g_xeB[q * Bb + u]      = xb0 + bb;
            g_xeB[q * Bb + u + 64] = xb1 + bb;
        }
        return;
    }

    int n0 = 200 + 2 * t;
    int n = n0 + slot;
    const int* rowix = use_psrc ? g_psrcd : g_rowidx;

    // w2 tile: 64 threads x 1 float4 (visibility via BN1's barriers)
    {
        const float4* w2p = (const float4*)(w2 + n * 256);
        ((float4*)sm->shw)[u] = w2p[u];
    }

    // uniform chunk trip count across both nodes of the block
    int rA = g_rsD[n0], rM = g_rsD[n0 + 1], rB = g_rsD[n0 + 2];
    int rs = slot ? rM : rA;
    int re = slot ? rB : rM;
    int trips = (max(rM - rA, rB - rM) + CH - 1) >> 6;

    u64 a0[8], a1[8];
    {
        const ulonglong2* bp = (const ulonglong2*)(b1 + n * 16);
#pragma unroll
        for (int k = 0; k < 4; k++) {
            ulonglong2 q = bp[k];
            a0[2 * k] = q.x; a0[2 * k + 1] = q.y;
            a1[2 * k] = q.x; a1[2 * k + 1] = q.y;
        }
    }

    // ---- gather ----
    for (int cc = 0; cc < trips; cc++) {
        int cbase = rs + cc * CH;
        int cnt = min(CH, re - cbase);     // may be <= 0 for lighter node
        __syncthreads();
        for (int i = u; i < cnt * 16; i += 64) sm->stage[i] = g_pw1[cbase * 16 + i];
        if (u < cnt) sm->sidx[u] = rowix[cbase + u];
        __syncthreads();
        for (int jb = 0; jb < cnt; jb += 4) {
            float x0[4], x1[4];
#pragma unroll
            for (int j = 0; j < 4; j++) {
                int jj = jb + j;
                if (jj < cnt) {
                    int r = sm->sidx[jj];
                    x0[j] = xe_rows[r + u];
                    x1[j] = xe_rows[r + u + 64];
                } else { x0[j] = 0.f; x1[j] = 0.f; }
            }
#pragma unroll
            for (int j = 0; j < 4; j++) {
                int jj = jb + j;
                if (jj < cnt) {
                    u64 v0 = splat2(x0[j]), v1 = splat2(x1[j]);
                    const ulonglong2* wp = (const ulonglong2*)&sm->stage[jj * 16];
                    ulonglong2 q0 = wp[0], q1 = wp[1], q2 = wp[2], q3 = wp[3];
                    a0[0] = fma2(q0.x, v0, a0[0]); a0[1] = fma2(q0.y, v0, a0[1]);
                    a0[2] = fma2(q1.x, v0, a0[2]); a0[3] = fma2(q1.y, v0, a0[3]);
                    a0[4] = fma2(q2.x, v0, a0[4]); a0[5] = fma2(q2.y, v0, a0[5]);
                    a0[6] = fma2(q3.x, v0, a0[6]); a0[7] = fma2(q3.y, v0, a0[7]);
                    a1[0] = fma2(q0.x, v1, a1[0]); a1[1] = fma2(q0.y, v1, a1[1]);
                    a1[2] = fma2(q1.x, v1, a1[2]); a1[3] = fma2(q1.y, v1, a1[3]);
                    a1[4] = fma2(q2.x, v1, a1[4]); a1[5] = fma2(q2.y, v1, a1[5]);
                    a1[6] = fma2(q3.x, v1, a1[6]); a1[7] = fma2(q3.y, v1, a1[7]);
                }
            }
        }
    }

    bn_elu2(a0, a1, n, u, g1, be1, sm);

    // ---- park h, then 16x16 matmul (own rows => no sync needed) ----
#pragma unroll
    for (int k = 0; k < 8; k++) {
        *(u64*)&sm->shh[u][2 * k]      = a0[k];
        *(u64*)&sm->shh[u + 64][2 * k] = a1[k];
    }

    u64 o0[8], o1[8];
    {
        const ulonglong2* bp = (const ulonglong2*)(b2 + n * 16);
#pragma unroll
        for (int k = 0; k < 4; k++) {
            ulonglong2 q = bp[k];
            o0[2 * k] = q.x; o0[2 * k + 1] = q.y;
            o1[2 * k] = q.x; o1[2 * k + 1] = q.y;
        }
    }
#pragma unroll
    for (int c = 0; c < 16; c++) {
        u64 v0 = splat2(sm->shh[u][c]);
        u64 v1 = splat2(sm->shh[u + 64][c]);
        const ulonglong2* wp = (const ulonglong2*)&sm->shw[c][0];
        ulonglong2 q0 = wp[0], q1 = wp[1], q2 = wp[2], q3 = wp[3];
        o0[0] = fma2(q0.x, v0, o0[0]); o0[1] = fma2(q0.y, v0, o0[1]);
        o0[2] = fma2(q1.x, v0, o0[2]); o0[3] = fma2(q1.y, v0, o0[3]);
        o0[4] = fma2(q2.x, v0, o0[4]); o0[5] = fma2(q2.y, v0, o0[5]);
        o0[6] = fma2(q3.x, v0, o0[6]); o0[7] = fma2(q3.y, v0, o0[7]);
        o1[0] = fma2(q0.x, v1, o1[0]); o1[1] = fma2(q0.y, v1, o1[1]);
        o1[2] = fma2(q1.x, v1, o1[2]); o1[3] = fma2(q1.y, v1, o1[3]);
        o1[4] = fma2(q2.x, v1, o1[4]); o1[5] = fma2(q2.y, v1, o1[5]);
        o1[6] = fma2(q3.x, v1, o1[6]); o1[7] = fma2(q3.y, v1, o1[7]);
    }

    bn_elu2(o0, o1, n, u, g2, be2, sm);

    // ---- scatter (live edges only) ----
    float xb0 = g_xT[n * Bb + u], xb1 = g_xT[n * Bb + u + 64];
    int qsA = g_rsS[n0], qsB = g_rsS[n0 + 1];
    int eA = qend[n0], eB = qend[n0 + 1];
    int qs = slot ? qsB : qsA;
    int qe = slot ? eB : eA;
    int qtrips = (max(eA - qsA, eB - qsB) + CH - 1) >> 6;
    for (int cc = 0; cc < qtrips; cc++) {
        int cbase = qs + cc * CH;
        int cnt = min(CH, qe - cbase);
        __syncthreads();
        for (int i = u; i < cnt * 16; i += 64) sm->stage[i] = g_pw3m[cbase * 16 + i];
        if (u < cnt) sm->sb3[u] = g_pb3[cbase + u];
        __syncthreads();
        for (int j = 0; j < cnt; j++) {
            const ulonglong2* wq = (const ulonglong2*)&sm->stage[j * 16];
            ulonglong2 q0 = wq[0], q1 = wq[1], q2 = wq[2], q3 = wq[3];
            u64 s0 = 0ULL, s1 = 0ULL;
            s0 = fma2(q0.x, o0[0], s0); s0 = fma2(q0.y, o0[1], s0);
            s0 = fma2(q1.x, o0[2], s0); s0 = fma2(q1.y, o0[3], s0);
            s0 = fma2(q2.x, o0[4], s0); s0 = fma2(q2.y, o0[5], s0);
            s0 = fma2(q3.x, o0[6], s0); s0 = fma2(q3.y, o0[7], s0);
            s1 = fma2(q0.x, o1[0], s1); s1 = fma2(q0.y, o1[1], s1);
            s1 = fma2(q1.x, o1[2], s1); s1 = fma2(q1.y, o1[3], s1);
            s1 = fma2(q2.x, o1[4], s1); s1 = fma2(q2.y, o1[5], s1);
            s1 = fma2(q3.x, o1[6], s1); s1 = fma2(q3.y, o1[7], s1);
            float p, q;
            unpack2(s0, p, q);
            float d0 = p + q;
            unpack2(s1, p, q);
            float d1 = p + q;
            float bb = sm->sb3[j];
            xe_out[(cbase + j) * Bb + u]      = xb0 + bb + d0;
            xe_out[(cbase + j) * Bb + u + 64] = xb1 + bb + d1;
        }
    }
}

// ---------------- final: compact sums, then coalesced output -----------------
__global__ void __launch_bounds__(128) k_sum(const float* __restrict__ xe) {
    int n = 1800 + blockIdx.x;
    int b = threadIdx.x;
    float s = 0.f;
    int rs = g_rsD[n], re = g_rsD[n + 1];
    for (int p = rs; p < re; p++) s += xe[g_rowidx[p] + b];
    g_osum[blockIdx.x * Bb + b] = s;
}

__global__ void __launch_bounds__(256) k_out(float* __restrict__ out) {
    int t = blockIdx.x * 256 + threadIdx.x;
    if (t < Bb * Nn) {
        int n = t % Nn;
        int b = t / Nn;
        out[t] = (n >= 1800) ? g_osum[(n - 1800) * Bb + b] : 0.0f;
    }
    if (t < Nn) { g_cntD[t] = 0; g_cntS[t] = 0; g_cntO[t] = 0; g_cntM[t] = 0; }
}

// ---------------- launch ----------------------------------------------------
extern "C" void kernel_launch(void* const* d_in, const int* in_sizes, int n_in,
                              void* d_out, int out_size) {
    const float* x   = (const float*)d_in[0];
    const float* w1  = (const float*)d_in[1];
    const float* b1  = (const float*)d_in[2];
    const float* w2  = (const float*)d_in[3];
    const float* b2  = (const float*)d_in[4];
    const float* w3  = (const float*)d_in[5];
    const float* b3  = (const float*)d_in[6];
    const float* g1  = (const float*)d_in[7];
    const float* be1 = (const float*)d_in[8];
    const float* g2  = (const float*)d_in[9];
    const float* be2 = (const float*)d_in[10];
    const int*   ei  = (const int*)d_in[11];
    float* out = (float*)d_out;

    const int* src = ei;
    const int* dst = ei + Ee;

    static float* xeA = nullptr;
    static float* xeB = nullptr;
    static float* xT  = nullptr;
    static int*   sb1 = nullptr;
    static int*   sb2 = nullptr;
    if (!xeA) {
        cudaGetSymbolAddress((void**)&xeA, g_xeA);
        cudaGetSymbolAddress((void**)&xeB, g_xeB);
        cudaGetSymbolAddress((void**)&xT,  g_xT);
        cudaGetSymbolAddress((void**)&sb1, g_sb1);
        cudaGetSymbolAddress((void**)&sb2, g_sb2);
        cudaFuncSetAttribute(k_layer,
            cudaFuncAttributePreferredSharedMemoryCarveout, 100);
    }

    dim3 gInit(63, 4);
    k_init<<<gInit, 256>>>(x, src, dst);
    k_scan<<<2, 1024>>>();
    k_build<<<(Ee + 255) / 256, 256>>>(w1, w3, b3, src, dst);

    k_layer<<<NLB + 200, 128>>>(xT,  1, xeA, sb2, b1, w2, b2, g1, be1, g2, be2);
    k_layer<<<NLB, 128>>>(xeA, 0, xeB, sb2, b1, w2, b2, g1, be1, g2, be2);
    k_layer<<<NLB, 128>>>(xeB, 0, xeA, sb2, b1, w2, b2, g1, be1, g2, be2);
    k_layer<<<NLB, 128>>>(xeA, 0, xeB, sb1, b1, w2, b2, g1, be1, g2, be2);

    k_sum<<<200, 128>>>(xeB);
    k_out<<<(Bb * Nn + 255) / 256, 256>>>(out);
}

// round 14
// speedup vs baseline: 1.0760x; 1.0283x over previous
#include <cuda_runtime.h>
#include <math.h>

#define Nn 2000
#define Ee 20000
#define Bb 128
#define EPS 1e-5f
#define CH 64          // edges staged per chunk
#define NLB 800        // layer blocks (2 nodes per block)

typedef unsigned long long u64;

__device__ __forceinline__ bool is_func(int n) { return n >= 200 && n < 1800; }

// ---- packed f32x2 helpers ---------------------------------------------------
__device__ __forceinline__ u64 fma2(u64 a, u64 b, u64 c) {
    u64 d;
    asm("fma.rn.f32x2 %0, %1, %2, %3;" : "=l"(d) : "l"(a), "l"(b), "l"(c));
    return d;
}
__device__ __forceinline__ u64 splat2(float x) {
    u64 d;
    unsigned r = __float_as_uint(x);
    asm("mov.b64 %0, {%1, %1};" : "=l"(d) : "r"(r));
    return d;
}
__device__ __forceinline__ void unpack2(u64 v, float& lo, float& hi) {
    unsigned a, b;
    asm("mov.b64 {%0, %1}, %2;" : "=r"(a), "=r"(b) : "l"(v));
    lo = __uint_as_float(a); hi = __uint_as_float(b);
}
__device__ __forceinline__ u64 pack2(float lo, float hi) {
    u64 d;
    unsigned a = __float_as_uint(lo), b = __float_as_uint(hi);
    asm("mov.b64 %0, {%1, %2};" : "=l"(d) : "r"(a), "r"(b));
    return d;
}
__device__ __forceinline__ u64 elu2(u64 v) {
    float lo, hi;
    unpack2(v, lo, hi);
    lo = lo > 0.f ? lo : (__expf(lo) - 1.0f);
    hi = hi > 0.f ? hi : (__expf(hi) - 1.0f);
    return pack2(lo, hi);
}

// ---------------- device scratch (allocation-free) --------------------------
__device__ float g_xT[Nn * Bb];
__device__ float g_xeA[Ee * Bb];
__device__ float g_xeB[Ee * Bb];
__device__ float g_pw1[Ee * 16];
__device__ float g_pw3m[Ee * 16];
__device__ float g_pb3[Ee];
__device__ int   g_psrcd[Ee];
__device__ int   g_rowidx[Ee];
__device__ float g_osum[200 * Bb];
__device__ int   g_cntD[Nn], g_cntS[Nn];   // zero at load; re-zeroed by k_out
__device__ int   g_cntO[Nn], g_cntM[Nn];
__device__ int   g_rsD[Nn + 1], g_rsS[Nn + 1];
__device__ int   g_curD[Nn];
__device__ int   g_cur0[Nn], g_cur1[Nn], g_cur2[Nn];
__device__ int   g_sb1[Nn];    // rsS + O   (scatter end, last layer)
__device__ int   g_sb2[Nn];    // rsS + O+M (scatter end, layers 0-2 / const)

// ---------------- preprocessing ---------------------------------------------
__global__ void __launch_bounds__(256) k_init(
        const float* __restrict__ x,
        const int* __restrict__ src, const int* __restrict__ dst) {
    __shared__ float tile[32][33];
    int bx = blockIdx.x, by = blockIdx.y;
    int tx = threadIdx.x & 31, ty = threadIdx.x >> 5;
    int n0 = bx * 32, b0 = by * 32;
#pragma unroll
    for (int k = 0; k < 32; k += 8) {
        int n = n0 + tx, b = b0 + ty + k;
        if (n < Nn) tile[ty + k][tx] = x[b * Nn + n];
    }
    __syncthreads();
#pragma unroll
    for (int k = 0; k < 32; k += 8) {
        int n = n0 + ty + k, b = b0 + tx;
        if (n < Nn) g_xT[n * Bb + b] = tile[tx][ty + k];
    }
    int t = (blockIdx.y * gridDim.x + blockIdx.x) * 256 + threadIdx.x;
    if (t < Ee) {
        int d = dst[t], s = src[t];
        atomicAdd(&g_cntD[d], 1);
        atomicAdd(&g_cntS[s], 1);
        if (d >= 1800)      atomicAdd(&g_cntO[s], 1);
        else if (d >= 200)  atomicAdd(&g_cntM[s], 1);
    }
}

__global__ void __launch_bounds__(1024) k_scan() {
    __shared__ int sh[2048];
    const int* cnt = blockIdx.x ? g_cntS : g_cntD;
    int* rs = blockIdx.x ? g_rsS : g_rsD;
    int t = threadIdx.x;
    sh[t]        = (t < Nn) ? cnt[t] : 0;
    sh[t + 1024] = (t + 1024 < Nn) ? cnt[t + 1024] : 0;
    __syncthreads();
    for (int off = 1; off < 2048; off <<= 1) {
        int v0 = (t >= off) ? sh[t - off] : 0;
        int v1 = (t + 1024 >= off) ? sh[t + 1024 - off] : 0;
        __syncthreads();
        sh[t] += v0;
        sh[t + 1024] += v1;
        __syncthreads();
    }
#pragma unroll
    for (int h = 0; h < 2; h++) {
        int i = t + h * 1024;
        if (i < Nn) {
            int v = (i == 0) ? 0 : sh[i - 1];
            rs[i] = v;
            if (blockIdx.x == 0) {
                g_curD[i] = v;
            } else {
                int o = g_cntO[i], m = g_cntM[i];
                g_cur0[i] = v;
                g_cur1[i] = v + o;
                g_cur2[i] = v + o + m;
                g_sb1[i]  = v + o;
                g_sb2[i]  = v + o + m;
            }
        }
    }
    if (t == 0) rs[Nn] = sh[Nn - 1];
}

// 128-thread blocks: shorter atomic->sync->copy chain, 157 blocks resident
__global__ void __launch_bounds__(128) k_build(
        const float* __restrict__ w1, const float* __restrict__ w3,
        const float* __restrict__ b3,
        const int* __restrict__ src, const int* __restrict__ dst) {
    __shared__ int sE[128], sPd[128], sPs[128];
    __shared__ float sFm[128];
    int e = blockIdx.x * 128 + threadIdx.x;
    int nEdge = min(128, Ee - blockIdx.x * 128);
    if (e < Ee) {
        int s = src[e], d = dst[e];
        int pd = atomicAdd(&g_curD[d], 1);
        int* cur = (d >= 1800) ? g_cur0 : ((d >= 200) ? g_cur1 : g_cur2);
        int ps = atomicAdd(&cur[s], 1);
        g_psrcd[pd]  = s * Bb;
        g_rowidx[pd] = ps * Bb;
        g_pb3[ps]    = b3[e];
        sE[threadIdx.x]  = e;
        sPd[threadIdx.x] = pd;
        sPs[threadIdx.x] = ps;
        sFm[threadIdx.x] = is_func(s) ? 1.0f : 0.0f;
    }
    __syncthreads();
    for (int i = threadIdx.x; i < nEdge * 16; i += 128) {
        int j = i >> 4, c = i & 15;
        int e2 = sE[j];
        g_pw1[sPd[j] * 16 + c]  = w1[e2 * 16 + c];
        g_pw3m[sPs[j] * 16 + c] = w3[e2 * 16 + c] * sFm[j];
    }
}

// ---------------- per-node shared block (no 9KB shh; 2-pass BN buffer) ------
struct __align__(16) NodeSm {
    union {
        float stage[CH * 16];      // 4096B weight staging (gather/scatter)
        float tr[64 * 17];         // 4352B BN transpose, row stride 17 (cf-free)
    };
    float shw[16][16];             // 1KB   w2 tile
    float shs[4][16], shs2[4][16];
    float shscale[16], shshift[16];
    int   sidx[CH];
    float sb3[CH];
};                                  // ~6.6KB per node, ~13.2KB per block

// ---------------- BN + ELU (64 threads/node, 2-pass transpose) ---------------
__device__ __forceinline__ void bn_elu2(u64* a0, u64* a1, int n, int u,
                                        const float* __restrict__ gamma,
                                        const float* __restrict__ beta,
                                        NodeSm* sm) {
    int c0 = u & 15, gg = u >> 4;      // 4 groups x 16 channels
    float s = 0.f, s2 = 0.f;
    // pass 1: lane-u rows (batch 0..63)
    __syncthreads();
#pragma unroll
    for (int k = 0; k < 8; k++) {
        float lo, hi;
        unpack2(a0[k], lo, hi);
        sm->tr[u * 17 + 2 * k]     = lo;
        sm->tr[u * 17 + 2 * k + 1] = hi;
    }
    __syncthreads();
#pragma unroll
    for (int k = 0; k < 16; k++) {
        float v = sm->tr[(gg * 16 + k) * 17 + c0];
        s += v; s2 += v * v;
    }
    // pass 2: lane-(u+64) rows (batch 64..127)
    __syncthreads();
#pragma unroll
    for (int k = 0; k < 8; k++) {
        float lo, hi;
        unpack2(a1[k], lo, hi);
        sm->tr[u * 17 + 2 * k]     = lo;
        sm->tr[u * 17 + 2 * k + 1] = hi;
    }
    __syncthreads();
#pragma unroll
    for (int k = 0; k < 16; k++) {
        float v = sm->tr[(gg * 16 + k) * 17 + c0];
        s += v; s2 += v * v;
    }
    sm->shs[gg][c0] = s;
    sm->shs2[gg][c0] = s2;
    __syncthreads();
    if (u < 16) {
        float S  = sm->shs[0][u] + sm->shs[1][u] + sm->shs[2][u] + sm->shs[3][u];
        float S2 = sm->shs2[0][u] + sm->shs2[1][u] + sm->shs2[2][u] + sm->shs2[3][u];
        float m   = S * (1.0f / 128.0f);
        float var = S2 * (1.0f / 128.0f) - m * m;
        float rsg = rsqrtf(var + EPS);
        float sc  = gamma[n * 16 + u] * rsg;
        sm->shscale[u] = sc;
        sm->shshift[u] = beta[n * 16 + u] - m * sc;
    }
    __syncthreads();
    const ulonglong2* scp = (const ulonglong2*)sm->shscale;
    const ulonglong2* shp = (const ulonglong2*)sm->shshift;
#pragma unroll
    for (int k2 = 0; k2 < 4; k2++) {
        ulonglong2 sc = scp[k2], sh = shp[k2];
        a0[2 * k2]     = elu2(fma2(a0[2 * k2],     sc.x, sh.x));
        a0[2 * k2 + 1] = elu2(fma2(a0[2 * k2 + 1], sc.y, sh.y));
        a1[2 * k2]     = elu2(fma2(a1[2 * k2],     sc.x, sh.x));
        a1[2 * k2 + 1] = elu2(fma2(a1[2 * k2 + 1], sc.y, sh.y));
    }
}

// matmul accumulate for one lane: o += h(c) * w2[c][:], h from packed regs
__device__ __forceinline__ void mm_lane(u64* o, const u64* a, const NodeSm* sm) {
#pragma unroll
    for (int k = 0; k < 8; k++) {
        float lo, hi;
        unpack2(a[k], lo, hi);
        {
            u64 v = splat2(lo);
            const ulonglong2* wp = (const ulonglong2*)&sm->shw[2 * k][0];
            ulonglong2 q0 = wp[0], q1 = wp[1], q2 = wp[2], q3 = wp[3];
            o[0] = fma2(q0.x, v, o[0]); o[1] = fma2(q0.y, v, o[1]);
            o[2] = fma2(q1.x, v, o[2]); o[3] = fma2(q1.y, v, o[3]);
            o[4] = fma2(q2.x, v, o[4]); o[5] = fma2(q2.y, v, o[5]);
            o[6] = fma2(q3.x, v, o[6]); o[7] = fma2(q3.y, v, o[7]);
        }
        {
            u64 v = splat2(hi);
            const ulonglong2* wp = (const ulonglong2*)&sm->shw[2 * k + 1][0];
            ulonglong2 q0 = wp[0], q1 = wp[1], q2 = wp[2], q3 = wp[3];
            o[0] = fma2(q0.x, v, o[0]); o[1] = fma2(q0.y, v, o[1]);
            o[2] = fma2(q1.x, v, o[2]); o[3] = fma2(q1.y, v, o[3]);
            o[4] = fma2(q2.x, v, o[4]); o[5] = fma2(q2.y, v, o[5]);
            o[6] = fma2(q3.x, v, o[6]); o[7] = fma2(q3.y, v, o[7]);
        }
    }
}

// ---------------- fused per-layer kernel: 2 nodes/block, 64 thr/node --------
__global__ void __launch_bounds__(128, 8) k_layer(
    const float* __restrict__ xe_rows, int use_psrc,
    float* __restrict__ xe_out, const int* __restrict__ qend,
    const float* __restrict__ b1, const float* __restrict__ w2,
    const float* __restrict__ b2,
    const float* __restrict__ g1, const float* __restrict__ be1,
    const float* __restrict__ g2, const float* __restrict__ be2) {
    __shared__ NodeSm smarr[2];
    int t = blockIdx.x;
    int tid = threadIdx.x;
    int slot = tid >> 6, u = tid & 63;
    NodeSm* sm = &smarr[slot];

    if (t >= NLB) {   // const-edge writers (layer-0 grid only), 2 per block
        int i = (t - NLB) * 2 + slot;
        int n = (i < 200) ? i : (1600 + i);
        float xb0 = g_xT[n * Bb + u], xb1 = g_xT[n * Bb + u + 64];
        int qs = g_rsS[n], qe = g_sb2[n];
        for (int q = qs; q < qe; q++) {
            float bb = g_pb3[q];
            g_xeA[q * Bb + u]      = xb0 + bb;
            g_xeA[q * Bb + u + 64] = xb1 + bb;
            g_xeB[q * Bb + u]      = xb0 + bb;
            g_xeB[q * Bb + u + 64] = xb1 + bb;
        }
        return;
    }

    int n0 = 200 + 2 * t;
    int n = n0 + slot;
    const int* rowix = use_psrc ? g_psrcd : g_rowidx;

    // w2 tile prefetch (visibility via first gather barrier)
    {
        const float4* w2p = (const float4*)(w2 + n * 256);
        ((float4*)sm->shw)[u] = w2p[u];
    }

    int rA = g_rsD[n0], rM = g_rsD[n0 + 1], rB = g_rsD[n0 + 2];
    int rs = slot ? rM : rA;
    int re = slot ? rB : rM;
    int trips = (max(rM - rA, rB - rM) + CH - 1) >> 6;

    u64 a0[8], a1[8];
    {
        const ulonglong2* bp = (const ulonglong2*)(b1 + n * 16);
#pragma unroll
        for (int k = 0; k < 4; k++) {
            ulonglong2 q = bp[k];
            a0[2 * k] = q.x; a0[2 * k + 1] = q.y;
            a1[2 * k] = q.x; a1[2 * k + 1] = q.y;
        }
    }

    // ---- gather ----
    for (int cc = 0; cc < trips; cc++) {
        int cbase = rs + cc * CH;
        int cnt = min(CH, re - cbase);
        __syncthreads();
        for (int i = u; i < cnt * 16; i += 64) sm->stage[i] = g_pw1[cbase * 16 + i];
        if (u < cnt) sm->sidx[u] = rowix[cbase + u];
        __syncthreads();
        for (int jb = 0; jb < cnt; jb += 4) {
            float x0[4], x1[4];
#pragma unroll
            for (int j = 0; j < 4; j++) {
                int jj = jb + j;
                if (jj < cnt) {
                    int r = sm->sidx[jj];
                    x0[j] = xe_rows[r + u];
                    x1[j] = xe_rows[r + u + 64];
                } else { x0[j] = 0.f; x1[j] = 0.f; }
            }
#pragma unroll
            for (int j = 0; j < 4; j++) {
                int jj = jb + j;
                if (jj < cnt) {
                    u64 v0 = splat2(x0[j]), v1 = splat2(x1[j]);
                    const ulonglong2* wp = (const ulonglong2*)&sm->stage[jj * 16];
                    ulonglong2 q0 = wp[0], q1 = wp[1], q2 = wp[2], q3 = wp[3];
                    a0[0] = fma2(q0.x, v0, a0[0]); a0[1] = fma2(q0.y, v0, a0[1]);
                    a0[2] = fma2(q1.x, v0, a0[2]); a0[3] = fma2(q1.y, v0, a0[3]);
                    a0[4] = fma2(q2.x, v0, a0[4]); a0[5] = fma2(q2.y, v0, a0[5]);
                    a0[6] = fma2(q3.x, v0, a0[6]); a0[7] = fma2(q3.y, v0, a0[7]);
                    a1[0] = fma2(q0.x, v1, a1[0]); a1[1] = fma2(q0.y, v1, a1[1]);
                    a1[2] = fma2(q1.x, v1, a1[2]); a1[3] = fma2(q1.y, v1, a1[3]);
                    a1[4] = fma2(q2.x, v1, a1[4]); a1[5] = fma2(q2.y, v1, a1[5]);
                    a1[6] = fma2(q3.x, v1, a1[6]); a1[7] = fma2(q3.y, v1, a1[7]);
                }
            }
        }
    }

    bn_elu2(a0, a1, n, u, g1, be1, sm);

    // ---- 16x16 matmul straight from registers (no smem h) ----
    u64 o0[8];
    {
        const ulonglong2* bp = (const ulonglong2*)(b2 + n * 16);
#pragma unroll
        for (int k = 0; k < 4; k++) {
            ulonglong2 q = bp[k];
            o0[2 * k] = q.x; o0[2 * k + 1] = q.y;
        }
    }
    mm_lane(o0, a0, sm);     // a0 dies here
    u64 o1[8];
    {
        const ulonglong2* bp = (const ulonglong2*)(b2 + n * 16);
#pragma unroll
        for (int k = 0; k < 4; k++) {
            ulonglong2 q = bp[k];
            o1[2 * k] = q.x; o1[2 * k + 1] = q.y;
        }
    }
    mm_lane(o1, a1, sm);     // a1 dies here

    bn_elu2(o0, o1, n, u, g2, be2, sm);

    // ---- scatter (live edges only) ----
    float xb0 = g_xT[n * Bb + u], xb1 = g_xT[n * Bb + u + 64];
    int qsA = g_rsS[n0], qsB = g_rsS[n0 + 1];
    int eA = qend[n0], eB = qend[n0 + 1];
    int qs = slot ? qsB : qsA;
    int qe = slot ? eB : eA;
    int qtrips = (max(eA - qsA, eB - qsB) + CH - 1) >> 6;
    for (int cc = 0; cc < qtrips; cc++) {
        int cbase = qs + cc * CH;
        int cnt = min(CH, qe - cbase);
        __syncthreads();
        for (int i = u; i < cnt * 16; i += 64) sm->stage[i] = g_pw3m[cbase * 16 + i];
        if (u < cnt) sm->sb3[u] = g_pb3[cbase + u];
        __syncthreads();
        for (int j = 0; j < cnt; j++) {
            const ulonglong2* wq = (const ulonglong2*)&sm->stage[j * 16];
            ulonglong2 q0 = wq[0], q1 = wq[1], q2 = wq[2], q3 = wq[3];
            u64 s0 = 0ULL, s1 = 0ULL;
            s0 = fma2(q0.x, o0[0], s0); s0 = fma2(q0.y, o0[1], s0);
            s0 = fma2(q1.x, o0[2], s0); s0 = fma2(q1.y, o0[3], s0);
            s0 = fma2(q2.x, o0[4], s0); s0 = fma2(q2.y, o0[5], s0);
            s0 = fma2(q3.x, o0[6], s0); s0 = fma2(q3.y, o0[7], s0);
            s1 = fma2(q0.x, o1[0], s1); s1 = fma2(q0.y, o1[1], s1);
            s1 = fma2(q1.x, o1[2], s1); s1 = fma2(q1.y, o1[3], s1);
            s1 = fma2(q2.x, o1[4], s1); s1 = fma2(q2.y, o1[5], s1);
            s1 = fma2(q3.x, o1[6], s1); s1 = fma2(q3.y, o1[7], s1);
            float p, q;
            unpack2(s0, p, q);
            float d0 = p + q;
            unpack2(s1, p, q);
            float d1 = p + q;
            float bb = sm->sb3[j];
            xe_out[(cbase + j) * Bb + u]      = xb0 + bb + d0;
            xe_out[(cbase + j) * Bb + u + 64] = xb1 + bb + d1;
        }
    }
}

// ---------------- final: compact sums, then coalesced output -----------------
__global__ void __launch_bounds__(128) k_sum(const float* __restrict__ xe) {
    int n = 1800 + blockIdx.x;
    int b = threadIdx.x;
    float s = 0.f;
    int rs = g_rsD[n], re = g_rsD[n + 1];
    for (int p = rs; p < re; p++) s += xe[g_rowidx[p] + b];
    g_osum[blockIdx.x * Bb + b] = s;
}

__global__ void __launch_bounds__(256) k_out(float* __restrict__ out) {
    int t = blockIdx.x * 256 + threadIdx.x;
    if (t < Bb * Nn) {
        int n = t % Nn;
        int b = t / Nn;
        out[t] = (n >= 1800) ? g_osum[(n - 1800) * Bb + b] : 0.0f;
    }
    if (t < Nn) { g_cntD[t] = 0; g_cntS[t] = 0; g_cntO[t] = 0; g_cntM[t] = 0; }
}

// ---------------- launch ----------------------------------------------------
extern "C" void kernel_launch(void* const* d_in, const int* in_sizes, int n_in,
                              void* d_out, int out_size) {
    const float* x   = (const float*)d_in[0];
    const float* w1  = (const float*)d_in[1];
    const float* b1  = (const float*)d_in[2];
    const float* w2  = (const float*)d_in[3];
    const float* b2  = (const float*)d_in[4];
    const float* w3  = (const float*)d_in[5];
    const float* b3  = (const float*)d_in[6];
    const float* g1  = (const float*)d_in[7];
    const float* be1 = (const float*)d_in[8];
    const float* g2  = (const float*)d_in[9];
    const float* be2 = (const float*)d_in[10];
    const int*   ei  = (const int*)d_in[11];
    float* out = (float*)d_out;

    const int* src = ei;
    const int* dst = ei + Ee;

    static float* xeA = nullptr;
    static float* xeB = nullptr;
    static float* xT  = nullptr;
    static int*   sb1 = nullptr;
    static int*   sb2 = nullptr;
    if (!xeA) {
        cudaGetSymbolAddress((void**)&xeA, g_xeA);
        cudaGetSymbolAddress((void**)&xeB, g_xeB);
        cudaGetSymbolAddress((void**)&xT,  g_xT);
        cudaGetSymbolAddress((void**)&sb1, g_sb1);
        cudaGetSymbolAddress((void**)&sb2, g_sb2);
        cudaFuncSetAttribute(k_layer,
            cudaFuncAttributePreferredSharedMemoryCarveout, 100);
    }

    dim3 gInit(63, 4);
    k_init<<<gInit, 256>>>(x, src, dst);
    k_scan<<<2, 1024>>>();
    k_build<<<(Ee + 127) / 128, 128>>>(w1, w3, b3, src, dst);

    k_layer<<<NLB + 200, 128>>>(xT,  1, xeA, sb2, b1, w2, b2, g1, be1, g2, be2);
    k_layer<<<NLB, 128>>>(xeA, 0, xeB, sb2, b1, w2, b2, g1, be1, g2, be2);
    k_layer<<<NLB, 128>>>(xeB, 0, xeA, sb2, b1, w2, b2, g1, be1, g2, be2);
    k_layer<<<NLB, 128>>>(xeA, 0, xeB, sb1, b1, w2, b2, g1, be1, g2, be2);

    k_sum<<<200, 128>>>(xeB);
    k_out<<<(Bb * Nn + 255) / 256, 256>>>(out);
}

// round 15
// speedup vs baseline: 1.1101x; 1.0316x over previous
#include <cuda_runtime.h>
#include <math.h>

#define Nn 2000
#define Ee 20000
#define Bb 128
#define EPS 1e-5f
#define CH 64          // edges staged per chunk

typedef unsigned long long u64;

__device__ __forceinline__ bool is_func(int n) { return n >= 200 && n < 1800; }

// ---- packed f32x2 helpers ---------------------------------------------------
__device__ __forceinline__ u64 fma2(u64 a, u64 b, u64 c) {
    u64 d;
    asm("fma.rn.f32x2 %0, %1, %2, %3;" : "=l"(d) : "l"(a), "l"(b), "l"(c));
    return d;
}
__device__ __forceinline__ u64 splat2(float x) {
    u64 d;
    unsigned r = __float_as_uint(x);
    asm("mov.b64 %0, {%1, %1};" : "=l"(d) : "r"(r));
    return d;
}
__device__ __forceinline__ void unpack2(u64 v, float& lo, float& hi) {
    unsigned a, b;
    asm("mov.b64 {%0, %1}, %2;" : "=r"(a), "=r"(b) : "l"(v));
    lo = __uint_as_float(a); hi = __uint_as_float(b);
}
__device__ __forceinline__ u64 pack2(float lo, float hi) {
    u64 d;
    unsigned a = __float_as_uint(lo), b = __float_as_uint(hi);
    asm("mov.b64 %0, {%1, %2};" : "=l"(d) : "r"(a), "r"(b));
    return d;
}
__device__ __forceinline__ u64 elu2(u64 v) {
    float lo, hi;
    unpack2(v, lo, hi);
    lo = lo > 0.f ? lo : (__expf(lo) - 1.0f);
    hi = hi > 0.f ? hi : (__expf(hi) - 1.0f);
    return pack2(lo, hi);
}

// ---------------- device scratch (allocation-free) --------------------------
__device__ float g_xT[Nn * Bb];
__device__ float g_xeA[Ee * Bb];
__device__ float g_xeB[Ee * Bb];
__device__ float g_pw1[Ee * 16];
__device__ float g_pw3m[Ee * 16];
__device__ float g_pb3[Ee];
__device__ int   g_psrcd[Ee];
__device__ int   g_rowidx[Ee];
__device__ float g_osum[200 * Bb];
__device__ int   g_cntD[Nn], g_cntS[Nn];   // zero at load; re-zeroed by k_out
__device__ int   g_cntO[Nn], g_cntM[Nn];
__device__ int   g_rsD[Nn + 1], g_rsS[Nn + 1];
__device__ int   g_curD[Nn];
__device__ int   g_cur0[Nn], g_cur1[Nn], g_cur2[Nn];
__device__ int   g_sb1[Nn];    // rsS + O   (scatter end, last layer)
__device__ int   g_sb2[Nn];    // rsS + O+M (scatter end, layers 0-2 / const)

// ---------------- preprocessing ---------------------------------------------
__global__ void __launch_bounds__(256) k_init(
        const float* __restrict__ x,
        const int* __restrict__ src, const int* __restrict__ dst) {
    __shared__ float tile[32][33];
    int bx = blockIdx.x, by = blockIdx.y;
    int tx = threadIdx.x & 31, ty = threadIdx.x >> 5;
    int n0 = bx * 32, b0 = by * 32;
#pragma unroll
    for (int k = 0; k < 32; k += 8) {
        int n = n0 + tx, b = b0 + ty + k;
        if (n < Nn) tile[ty + k][tx] = x[b * Nn + n];
    }
    __syncthreads();
#pragma unroll
    for (int k = 0; k < 32; k += 8) {
        int n = n0 + ty + k, b = b0 + tx;
        if (n < Nn) g_xT[n * Bb + b] = tile[tx][ty + k];
    }
    int t = (blockIdx.y * gridDim.x + blockIdx.x) * 256 + threadIdx.x;
    if (t < Ee) {
        int d = dst[t], s = src[t];
        atomicAdd(&g_cntD[d], 1);
        atomicAdd(&g_cntS[s], 1);
        if (d >= 1800)      atomicAdd(&g_cntO[s], 1);
        else if (d >= 200)  atomicAdd(&g_cntM[s], 1);
    }
}

__global__ void __launch_bounds__(1024) k_scan() {
    __shared__ int sh[2048];
    const int* cnt = blockIdx.x ? g_cntS : g_cntD;
    int* rs = blockIdx.x ? g_rsS : g_rsD;
    int t = threadIdx.x;
    sh[t]        = (t < Nn) ? cnt[t] : 0;
    sh[t + 1024] = (t + 1024 < Nn) ? cnt[t + 1024] : 0;
    __syncthreads();
    for (int off = 1; off < 2048; off <<= 1) {
        int v0 = (t >= off) ? sh[t - off] : 0;
        int v1 = (t + 1024 >= off) ? sh[t + 1024 - off] : 0;
        __syncthreads();
        sh[t] += v0;
        sh[t + 1024] += v1;
        __syncthreads();
    }
#pragma unroll
    for (int h = 0; h < 2; h++) {
        int i = t + h * 1024;
        if (i < Nn) {
            int v = (i == 0) ? 0 : sh[i - 1];
            rs[i] = v;
            if (blockIdx.x == 0) {
                g_curD[i] = v;
            } else {
                int o = g_cntO[i], m = g_cntM[i];
                g_cur0[i] = v;
                g_cur1[i] = v + o;
                g_cur2[i] = v + o + m;
                g_sb1[i]  = v + o;
                g_sb2[i]  = v + o + m;
            }
        }
    }
    if (t == 0) rs[Nn] = sh[Nn - 1];
}

__global__ void __launch_bounds__(128) k_build(
        const float* __restrict__ w1, const float* __restrict__ w3,
        const float* __restrict__ b3,
        const int* __restrict__ src, const int* __restrict__ dst) {
    __shared__ int sE[128], sPd[128], sPs[128];
    __shared__ float sFm[128];
    int e = blockIdx.x * 128 + threadIdx.x;
    int nEdge = min(128, Ee - blockIdx.x * 128);
    if (e < Ee) {
        int s = src[e], d = dst[e];
        int pd = atomicAdd(&g_curD[d], 1);
        int* cur = (d >= 1800) ? g_cur0 : ((d >= 200) ? g_cur1 : g_cur2);
        int ps = atomicAdd(&cur[s], 1);
        g_psrcd[pd]  = s * Bb;
        g_rowidx[pd] = ps * Bb;
        g_pb3[ps]    = b3[e];
        sE[threadIdx.x]  = e;
        sPd[threadIdx.x] = pd;
        sPs[threadIdx.x] = ps;
        sFm[threadIdx.x] = is_func(s) ? 1.0f : 0.0f;
    }
    __syncthreads();
    for (int i = threadIdx.x; i < nEdge * 16; i += 128) {
        int j = i >> 4, c = i & 15;
        int e2 = sE[j];
        g_pw1[sPd[j] * 16 + c]  = w1[e2 * 16 + c];
        g_pw3m[sPs[j] * 16 + c] = w3[e2 * 16 + c] * sFm[j];
    }
}

// ---------------- per-node shared block (one per 64-thread block) -----------
struct __align__(16) NodeSm {
    union {
        float stage[CH * 16];      // 4096B weight staging (gather/scatter)
        float tr[64 * 17];         // 4352B BN transpose, row stride 17
    };
    float shw[16][16];             // 1KB   w2 tile
    float shs[4][16], shs2[4][16];
    float shscale[16], shshift[16];
    int   sidx[CH];
    float sb3[CH];
};                                  // ~6.6KB per block

// ---------------- BN + ELU (64 threads, 2-pass transpose) --------------------
__device__ __forceinline__ void bn_elu2(u64* a0, u64* a1, int n, int u,
                                        const float* __restrict__ gamma,
                                        const float* __restrict__ beta,
                                        NodeSm* sm) {
    int c0 = u & 15, gg = u >> 4;      // 4 groups x 16 channels
    float s = 0.f, s2 = 0.f;
    __syncthreads();
#pragma unroll
    for (int k = 0; k < 8; k++) {
        float lo, hi;
        unpack2(a0[k], lo, hi);
        sm->tr[u * 17 + 2 * k]     = lo;
        sm->tr[u * 17 + 2 * k + 1] = hi;
    }
    __syncthreads();
#pragma unroll
    for (int k = 0; k < 16; k++) {
        float v = sm->tr[(gg * 16 + k) * 17 + c0];
        s += v; s2 += v * v;
    }
    __syncthreads();
#pragma unroll
    for (int k = 0; k < 8; k++) {
        float lo, hi;
        unpack2(a1[k], lo, hi);
        sm->tr[u * 17 + 2 * k]     = lo;
        sm->tr[u * 17 + 2 * k + 1] = hi;
    }
    __syncthreads();
#pragma unroll
    for (int k = 0; k < 16; k++) {
        float v = sm->tr[(gg * 16 + k) * 17 + c0];
        s += v; s2 += v * v;
    }
    sm->shs[gg][c0] = s;
    sm->shs2[gg][c0] = s2;
    __syncthreads();
    if (u < 16) {
        float S  = sm->shs[0][u] + sm->shs[1][u] + sm->shs[2][u] + sm->shs[3][u];
        float S2 = sm->shs2[0][u] + sm->shs2[1][u] + sm->shs2[2][u] + sm->shs2[3][u];
        float m   = S * (1.0f / 128.0f);
        float var = S2 * (1.0f / 128.0f) - m * m;
        float rsg = rsqrtf(var + EPS);
        float sc  = gamma[n * 16 + u] * rsg;
        sm->shscale[u] = sc;
        sm->shshift[u] = beta[n * 16 + u] - m * sc;
    }
    __syncthreads();
    const ulonglong2* scp = (const ulonglong2*)sm->shscale;
    const ulonglong2* shp = (const ulonglong2*)sm->shshift;
#pragma unroll
    for (int k2 = 0; k2 < 4; k2++) {
        ulonglong2 sc = scp[k2], sh = shp[k2];
        a0[2 * k2]     = elu2(fma2(a0[2 * k2],     sc.x, sh.x));
        a0[2 * k2 + 1] = elu2(fma2(a0[2 * k2 + 1], sc.y, sh.y));
        a1[2 * k2]     = elu2(fma2(a1[2 * k2],     sc.x, sh.x));
        a1[2 * k2 + 1] = elu2(fma2(a1[2 * k2 + 1], sc.y, sh.y));
    }
}

// matmul accumulate for one lane: o += h(c) * w2[c][:], h from packed regs
__device__ __forceinline__ void mm_lane(u64* o, const u64* a, const NodeSm* sm) {
#pragma unroll
    for (int k = 0; k < 8; k++) {
        float lo, hi;
        unpack2(a[k], lo, hi);
        {
            u64 v = splat2(lo);
            const ulonglong2* wp = (const ulonglong2*)&sm->shw[2 * k][0];
            ulonglong2 q0 = wp[0], q1 = wp[1], q2 = wp[2], q3 = wp[3];
            o[0] = fma2(q0.x, v, o[0]); o[1] = fma2(q0.y, v, o[1]);
            o[2] = fma2(q1.x, v, o[2]); o[3] = fma2(q1.y, v, o[3]);
            o[4] = fma2(q2.x, v, o[4]); o[5] = fma2(q2.y, v, o[5]);
            o[6] = fma2(q3.x, v, o[6]); o[7] = fma2(q3.y, v, o[7]);
        }
        {
            u64 v = splat2(hi);
            const ulonglong2* wp = (const ulonglong2*)&sm->shw[2 * k + 1][0];
            ulonglong2 q0 = wp[0], q1 = wp[1], q2 = wp[2], q3 = wp[3];
            o[0] = fma2(q0.x, v, o[0]); o[1] = fma2(q0.y, v, o[1]);
            o[2] = fma2(q1.x, v, o[2]); o[3] = fma2(q1.y, v, o[3]);
            o[4] = fma2(q2.x, v, o[4]); o[5] = fma2(q2.y, v, o[5]);
            o[6] = fma2(q3.x, v, o[6]); o[7] = fma2(q3.y, v, o[7]);
        }
    }
}

// ---------------- fused per-layer kernel: 1 node per 64-thread block --------
__global__ void __launch_bounds__(64, 16) k_layer(
    const float* __restrict__ xe_rows, int use_psrc,
    float* __restrict__ xe_out, const int* __restrict__ qend,
    const float* __restrict__ b1, const float* __restrict__ w2,
    const float* __restrict__ b2,
    const float* __restrict__ g1, const float* __restrict__ be1,
    const float* __restrict__ g2, const float* __restrict__ be2) {
    __shared__ NodeSm smx;
    NodeSm* sm = &smx;
    int t = blockIdx.x;
    int u = threadIdx.x;          // 0..63; lanes u and u+64

    if (t >= 1600) {   // const-edge writers (layer-0 grid only)
        int i = t - 1600;
        int n = (i < 200) ? i : (1600 + i);
        float xb0 = g_xT[n * Bb + u], xb1 = g_xT[n * Bb + u + 64];
        int qs = g_rsS[n], qe = g_sb2[n];
        for (int q = qs; q < qe; q++) {
            float bb = g_pb3[q];
            g_xeA[q * Bb + u]      = xb0 + bb;
            g_xeA[q * Bb + u + 64] = xb1 + bb;
            g_xeB[q * Bb + u]      = xb0 + bb;
            g_xeB[q * Bb + u + 64] = xb1 + bb;
        }
        return;
    }

    int n = 200 + t;
    const int* rowix = use_psrc ? g_psrcd : g_rowidx;

    // w2 tile prefetch (visibility via first gather barrier)
    {
        const float4* w2p = (const float4*)(w2 + n * 256);
        ((float4*)sm->shw)[u] = w2p[u];
    }

    int rs = g_rsD[n], re = g_rsD[n + 1];

    u64 a0[8], a1[8];
    {
        const ulonglong2* bp = (const ulonglong2*)(b1 + n * 16);
#pragma unroll
        for (int k = 0; k < 4; k++) {
            ulonglong2 q = bp[k];
            a0[2 * k] = q.x; a0[2 * k + 1] = q.y;
            a1[2 * k] = q.x; a1[2 * k + 1] = q.y;
        }
    }

    // ---- gather ----
    for (int cbase = rs; cbase < re; cbase += CH) {
        int cnt = min(CH, re - cbase);
        __syncthreads();
        for (int i = u; i < cnt * 16; i += 64) sm->stage[i] = g_pw1[cbase * 16 + i];
        if (u < cnt) sm->sidx[u] = rowix[cbase + u];
        __syncthreads();
        for (int jb = 0; jb < cnt; jb += 4) {
            float x0[4], x1[4];
#pragma unroll
            for (int j = 0; j < 4; j++) {
                int jj = jb + j;
                if (jj < cnt) {
                    int r = sm->sidx[jj];
                    x0[j] = xe_rows[r + u];
                    x1[j] = xe_rows[r + u + 64];
                } else { x0[j] = 0.f; x1[j] = 0.f; }
            }
#pragma unroll
            for (int j = 0; j < 4; j++) {
                int jj = jb + j;
                if (jj < cnt) {
                    u64 v0 = splat2(x0[j]), v1 = splat2(x1[j]);
                    const ulonglong2* wp = (const ulonglong2*)&sm->stage[jj * 16];
                    ulonglong2 q0 = wp[0], q1 = wp[1], q2 = wp[2], q3 = wp[3];
                    a0[0] = fma2(q0.x, v0, a0[0]); a0[1] = fma2(q0.y, v0, a0[1]);
                    a0[2] = fma2(q1.x, v0, a0[2]); a0[3] = fma2(q1.y, v0, a0[3]);
                    a0[4] = fma2(q2.x, v0, a0[4]); a0[5] = fma2(q2.y, v0, a0[5]);
                    a0[6] = fma2(q3.x, v0, a0[6]); a0[7] = fma2(q3.y, v0, a0[7]);
                    a1[0] = fma2(q0.x, v1, a1[0]); a1[1] = fma2(q0.y, v1, a1[1]);
                    a1[2] = fma2(q1.x, v1, a1[2]); a1[3] = fma2(q1.y, v1, a1[3]);
                    a1[4] = fma2(q2.x, v1, a1[4]); a1[5] = fma2(q2.y, v1, a1[5]);
                    a1[6] = fma2(q3.x, v1, a1[6]); a1[7] = fma2(q3.y, v1, a1[7]);
                }
            }
        }
    }

    bn_elu2(a0, a1, n, u, g1, be1, sm);

    // ---- 16x16 matmul straight from registers ----
    u64 o0[8];
    {
        const ulonglong2* bp = (const ulonglong2*)(b2 + n * 16);
#pragma unroll
        for (int k = 0; k < 4; k++) {
            ulonglong2 q = bp[k];
            o0[2 * k] = q.x; o0[2 * k + 1] = q.y;
        }
    }
    mm_lane(o0, a0, sm);     // a0 dies here
    u64 o1[8];
    {
        const ulonglong2* bp = (const ulonglong2*)(b2 + n * 16);
#pragma unroll
        for (int k = 0; k < 4; k++) {
            ulonglong2 q = bp[k];
            o1[2 * k] = q.x; o1[2 * k + 1] = q.y;
        }
    }
    mm_lane(o1, a1, sm);     // a1 dies here

    bn_elu2(o0, o1, n, u, g2, be2, sm);

    // ---- scatter (live edges only) ----
    float xb0 = g_xT[n * Bb + u], xb1 = g_xT[n * Bb + u + 64];
    int qs = g_rsS[n], qe = qend[n];
    for (int cbase = qs; cbase < qe; cbase += CH) {
        int cnt = min(CH, qe - cbase);
        __syncthreads();
        for (int i = u; i < cnt * 16; i += 64) sm->stage[i] = g_pw3m[cbase * 16 + i];
        if (u < cnt) sm->sb3[u] = g_pb3[cbase + u];
        __syncthreads();
        for (int j = 0; j < cnt; j++) {
            const ulonglong2* wq = (const ulonglong2*)&sm->stage[j * 16];
            ulonglong2 q0 = wq[0], q1 = wq[1], q2 = wq[2], q3 = wq[3];
            u64 s0 = 0ULL, s1 = 0ULL;
            s0 = fma2(q0.x, o0[0], s0); s0 = fma2(q0.y, o0[1], s0);
            s0 = fma2(q1.x, o0[2], s0); s0 = fma2(q1.y, o0[3], s0);
            s0 = fma2(q2.x, o0[4], s0); s0 = fma2(q2.y, o0[5], s0);
            s0 = fma2(q3.x, o0[6], s0); s0 = fma2(q3.y, o0[7], s0);
            s1 = fma2(q0.x, o1[0], s1); s1 = fma2(q0.y, o1[1], s1);
            s1 = fma2(q1.x, o1[2], s1); s1 = fma2(q1.y, o1[3], s1);
            s1 = fma2(q2.x, o1[4], s1); s1 = fma2(q2.y, o1[5], s1);
            s1 = fma2(q3.x, o1[6], s1); s1 = fma2(q3.y, o1[7], s1);
            float p, q;
            unpack2(s0, p, q);
            float d0 = p + q;
            unpack2(s1, p, q);
            float d1 = p + q;
            float bb = sm->sb3[j];
            xe_out[(cbase + j) * Bb + u]      = xb0 + bb + d0;
            xe_out[(cbase + j) * Bb + u + 64] = xb1 + bb + d1;
        }
    }
}

// ---------------- final: compact sums, then coalesced output -----------------
__global__ void __launch_bounds__(128) k_sum(const float* __restrict__ xe) {
    int n = 1800 + blockIdx.x;
    int b = threadIdx.x;
    float s = 0.f;
    int rs = g_rsD[n], re = g_rsD[n + 1];
    for (int p = rs; p < re; p++) s += xe[g_rowidx[p] + b];
    g_osum[blockIdx.x * Bb + b] = s;
}

__global__ void __launch_bounds__(256) k_out(float* __restrict__ out) {
    int t = blockIdx.x * 256 + threadIdx.x;
    if (t < Bb * Nn) {
        int n = t % Nn;
        int b = t / Nn;
        out[t] = (n >= 1800) ? g_osum[(n - 1800) * Bb + b] : 0.0f;
    }
    if (t < Nn) { g_cntD[t] = 0; g_cntS[t] = 0; g_cntO[t] = 0; g_cntM[t] = 0; }
}

// ---------------- launch ----------------------------------------------------
extern "C" void kernel_launch(void* const* d_in, const int* in_sizes, int n_in,
                              void* d_out, int out_size) {
    const float* x   = (const float*)d_in[0];
    const float* w1  = (const float*)d_in[1];
    const float* b1  = (const float*)d_in[2];
    const float* w2  = (const float*)d_in[3];
    const float* b2  = (const float*)d_in[4];
    const float* w3  = (const float*)d_in[5];
    const float* b3  = (const float*)d_in[6];
    const float* g1  = (const float*)d_in[7];
    const float* be1 = (const float*)d_in[8];
    const float* g2  = (const float*)d_in[9];
    const float* be2 = (const float*)d_in[10];
    const int*   ei  = (const int*)d_in[11];
    float* out = (float*)d_out;

    const int* src = ei;
    const int* dst = ei + Ee;

    static float* xeA = nullptr;
    static float* xeB = nullptr;
    static float* xT  = nullptr;
    static int*   sb1 = nullptr;
    static int*   sb2 = nullptr;
    if (!xeA) {
        cudaGetSymbolAddress((void**)&xeA, g_xeA);
        cudaGetSymbolAddress((void**)&xeB, g_xeB);
        cudaGetSymbolAddress((void**)&xT,  g_xT);
        cudaGetSymbolAddress((void**)&sb1, g_sb1);
        cudaGetSymbolAddress((void**)&sb2, g_sb2);
        cudaFuncSetAttribute(k_layer,
            cudaFuncAttributePreferredSharedMemoryCarveout, 100);
    }

    dim3 gInit(63, 4);
    k_init<<<gInit, 256>>>(x, src, dst);
    k_scan<<<2, 1024>>>();
    k_build<<<(Ee + 127) / 128, 128>>>(w1, w3, b3, src, dst);

    k_layer<<<2000, 64>>>(xT,  1, xeA, sb2, b1, w2, b2, g1, be1, g2, be2);
    k_layer<<<1600, 64>>>(xeA, 0, xeB, sb2, b1, w2, b2, g1, be1, g2, be2);
    k_layer<<<1600, 64>>>(xeB, 0, xeA, sb2, b1, w2, b2, g1, be1, g2, be2);
    k_layer<<<1600, 64>>>(xeA, 0, xeB, sb1, b1, w2, b2, g1, be1, g2, be2);

    k_sum<<<200, 128>>>(xeB);
    k_out<<<(Bb * Nn + 255) / 256, 256>>>(out);
}

// round 16
// speedup vs baseline: 1.1981x; 1.0793x over previous
#include <cuda_runtime.h>
#include <math.h>

#define Nn 2000
#define Ee 20000
#define Bb 128
#define EPS 1e-5f
#define CH 64          // edges staged per chunk

typedef unsigned long long u64;

__device__ __forceinline__ bool is_func(int n) { return n >= 200 && n < 1800; }

// ---- packed f32x2 helpers ---------------------------------------------------
__device__ __forceinline__ u64 fma2(u64 a, u64 b, u64 c) {
    u64 d;
    asm("fma.rn.f32x2 %0, %1, %2, %3;" : "=l"(d) : "l"(a), "l"(b), "l"(c));
    return d;
}
__device__ __forceinline__ u64 splat2(float x) {
    u64 d;
    unsigned r = __float_as_uint(x);
    asm("mov.b64 %0, {%1, %1};" : "=l"(d) : "r"(r));
    return d;
}
__device__ __forceinline__ void unpack2(u64 v, float& lo, float& hi) {
    unsigned a, b;
    asm("mov.b64 {%0, %1}, %2;" : "=r"(a), "=r"(b) : "l"(v));
    lo = __uint_as_float(a); hi = __uint_as_float(b);
}
__device__ __forceinline__ u64 pack2(float lo, float hi) {
    u64 d;
    unsigned a = __float_as_uint(lo), b = __float_as_uint(hi);
    asm("mov.b64 %0, {%1, %2};" : "=l"(d) : "r"(a), "r"(b));
    return d;
}
__device__ __forceinline__ u64 elu2(u64 v) {
    float lo, hi;
    unpack2(v, lo, hi);
    lo = lo > 0.f ? lo : (__expf(lo) - 1.0f);
    hi = hi > 0.f ? hi : (__expf(hi) - 1.0f);
    return pack2(lo, hi);
}

// ---------------- device scratch (allocation-free) --------------------------
__device__ float g_xT[Nn * Bb];
__device__ float g_xeA[Ee * Bb];
__device__ float g_xeB[Ee * Bb];
__device__ float g_pw1[Ee * 16];
__device__ float g_pw3m[Ee * 16];
__device__ float g_pb3[Ee];
__device__ int   g_psrcd[Ee];
__device__ int   g_rowidx[Ee];
__device__ float g_osum[200 * Bb];
__device__ int   g_cntD[Nn], g_cntS[Nn];   // zero at load; re-zeroed by k_out
__device__ int   g_cntO[Nn], g_cntM[Nn];
__device__ int   g_rsD[Nn + 1], g_rsS[Nn + 1];
__device__ int   g_curD[Nn];
__device__ int   g_cur0[Nn], g_cur1[Nn], g_cur2[Nn];
__device__ int   g_sb1[Nn];    // rsS + O   (scatter end, last layer)
__device__ int   g_sb2[Nn];    // rsS + O+M (scatter end, layers 0-2 / const)

// ---------------- preprocessing ---------------------------------------------
__global__ void __launch_bounds__(256) k_init(
        const float* __restrict__ x,
        const int* __restrict__ src, const int* __restrict__ dst) {
    __shared__ float tile[32][33];
    int bx = blockIdx.x, by = blockIdx.y;
    int tx = threadIdx.x & 31, ty = threadIdx.x >> 5;
    int n0 = bx * 32, b0 = by * 32;
#pragma unroll
    for (int k = 0; k < 32; k += 8) {
        int n = n0 + tx, b = b0 + ty + k;
        if (n < Nn) tile[ty + k][tx] = x[b * Nn + n];
    }
    __syncthreads();
#pragma unroll
    for (int k = 0; k < 32; k += 8) {
        int n = n0 + ty + k, b = b0 + tx;
        if (n < Nn) g_xT[n * Bb + b] = tile[tx][ty + k];
    }
    int t = (blockIdx.y * gridDim.x + blockIdx.x) * 256 + threadIdx.x;
    if (t < Ee) {
        int d = dst[t], s = src[t];
        atomicAdd(&g_cntD[d], 1);
        atomicAdd(&g_cntS[s], 1);
        if (d >= 1800)      atomicAdd(&g_cntO[s], 1);
        else if (d >= 200)  atomicAdd(&g_cntM[s], 1);
    }
}

__global__ void __launch_bounds__(1024) k_scan() {
    __shared__ int sh[2048];
    const int* cnt = blockIdx.x ? g_cntS : g_cntD;
    int* rs = blockIdx.x ? g_rsS : g_rsD;
    int t = threadIdx.x;
    sh[t]        = (t < Nn) ? cnt[t] : 0;
    sh[t + 1024] = (t + 1024 < Nn) ? cnt[t + 1024] : 0;
    __syncthreads();
    for (int off = 1; off < 2048; off <<= 1) {
        int v0 = (t >= off) ? sh[t - off] : 0;
        int v1 = (t + 1024 >= off) ? sh[t + 1024 - off] : 0;
        __syncthreads();
        sh[t] += v0;
        sh[t + 1024] += v1;
        __syncthreads();
    }
#pragma unroll
    for (int h = 0; h < 2; h++) {
        int i = t + h * 1024;
        if (i < Nn) {
            int v = (i == 0) ? 0 : sh[i - 1];
            rs[i] = v;
            if (blockIdx.x == 0) {
                g_curD[i] = v;
            } else {
                int o = g_cntO[i], m = g_cntM[i];
                g_cur0[i] = v;
                g_cur1[i] = v + o;
                g_cur2[i] = v + o + m;
                g_sb1[i]  = v + o;
                g_sb2[i]  = v + o + m;
            }
        }
    }
    if (t == 0) rs[Nn] = sh[Nn - 1];
}

__global__ void __launch_bounds__(128) k_build(
        const float* __restrict__ w1, const float* __restrict__ w3,
        const float* __restrict__ b3,
        const int* __restrict__ src, const int* __restrict__ dst) {
    __shared__ int sE[128], sPd[128], sPs[128];
    __shared__ float sFm[128];
    int e = blockIdx.x * 128 + threadIdx.x;
    int nEdge = min(128, Ee - blockIdx.x * 128);
    if (e < Ee) {
        int s = src[e], d = dst[e];
        int pd = atomicAdd(&g_curD[d], 1);
        int* cur = (d >= 1800) ? g_cur0 : ((d >= 200) ? g_cur1 : g_cur2);
        int ps = atomicAdd(&cur[s], 1);
        g_psrcd[pd]  = s * Bb;
        g_rowidx[pd] = ps * Bb;
        g_pb3[ps]    = b3[e];
        sE[threadIdx.x]  = e;
        sPd[threadIdx.x] = pd;
        sPs[threadIdx.x] = ps;
        sFm[threadIdx.x] = is_func(s) ? 1.0f : 0.0f;
    }
    __syncthreads();
    for (int i = threadIdx.x; i < nEdge * 16; i += 128) {
        int j = i >> 4, c = i & 15;
        int e2 = sE[j];
        g_pw1[sPd[j] * 16 + c]  = w1[e2 * 16 + c];
        g_pw3m[sPs[j] * 16 + c] = w3[e2 * 16 + c] * sFm[j];
    }
}

// ---------------- per-node shared block (one per 64-thread block) -----------
struct __align__(16) NodeSm {
    union {
        float stage[CH * 16];      // 4096B weight staging (gather/scatter)
        float tr[64 * 17];         // 4352B BN transpose, row stride 17
    };
    float shw[16][16];             // 1KB   w2 tile
    float shs[4][16], shs2[4][16];
    float shscale[16], shshift[16];
    int   sidx[CH];
    float sb3[CH];
};                                  // ~6.6KB per block

// ---------------- BN + ELU (64 threads, 2-pass transpose) --------------------
__device__ __forceinline__ void bn_elu2(u64* a0, u64* a1, int n, int u,
                                        const float* __restrict__ gamma,
                                        const float* __restrict__ beta,
                                        NodeSm* sm) {
    int c0 = u & 15, gg = u >> 4;      // 4 groups x 16 channels
    float s = 0.f, s2 = 0.f;
    __syncthreads();
#pragma unroll
    for (int k = 0; k < 8; k++) {
        float lo, hi;
        unpack2(a0[k], lo, hi);
        sm->tr[u * 17 + 2 * k]     = lo;
        sm->tr[u * 17 + 2 * k + 1] = hi;
    }
    __syncthreads();
#pragma unroll
    for (int k = 0; k < 16; k++) {
        float v = sm->tr[(gg * 16 + k) * 17 + c0];
        s += v; s2 += v * v;
    }
    __syncthreads();
#pragma unroll
    for (int k = 0; k < 8; k++) {
        float lo, hi;
        unpack2(a1[k], lo, hi);
        sm->tr[u * 17 + 2 * k]     = lo;
        sm->tr[u * 17 + 2 * k + 1] = hi;
    }
    __syncthreads();
#pragma unroll
    for (int k = 0; k < 16; k++) {
        float v = sm->tr[(gg * 16 + k) * 17 + c0];
        s += v; s2 += v * v;
    }
    sm->shs[gg][c0] = s;
    sm->shs2[gg][c0] = s2;
    __syncthreads();
    if (u < 16) {
        float S  = sm->shs[0][u] + sm->shs[1][u] + sm->shs[2][u] + sm->shs[3][u];
        float S2 = sm->shs2[0][u] + sm->shs2[1][u] + sm->shs2[2][u] + sm->shs2[3][u];
        float m   = S * (1.0f / 128.0f);
        float var = S2 * (1.0f / 128.0f) - m * m;
        float rsg = rsqrtf(var + EPS);
        float sc  = gamma[n * 16 + u] * rsg;
        sm->shscale[u] = sc;
        sm->shshift[u] = beta[n * 16 + u] - m * sc;
    }
    __syncthreads();
    const ulonglong2* scp = (const ulonglong2*)sm->shscale;
    const ulonglong2* shp = (const ulonglong2*)sm->shshift;
#pragma unroll
    for (int k2 = 0; k2 < 4; k2++) {
        ulonglong2 sc = scp[k2], sh = shp[k2];
        a0[2 * k2]     = elu2(fma2(a0[2 * k2],     sc.x, sh.x));
        a0[2 * k2 + 1] = elu2(fma2(a0[2 * k2 + 1], sc.y, sh.y));
        a1[2 * k2]     = elu2(fma2(a1[2 * k2],     sc.x, sh.x));
        a1[2 * k2 + 1] = elu2(fma2(a1[2 * k2 + 1], sc.y, sh.y));
    }
}

// matmul accumulate for one lane: o += h(c) * w2[c][:], h from packed regs
__device__ __forceinline__ void mm_lane(u64* o, const u64* a, const NodeSm* sm) {
#pragma unroll
    for (int k = 0; k < 8; k++) {
        float lo, hi;
        unpack2(a[k], lo, hi);
        {
            u64 v = splat2(lo);
            const ulonglong2* wp = (const ulonglong2*)&sm->shw[2 * k][0];
            ulonglong2 q0 = wp[0], q1 = wp[1], q2 = wp[2], q3 = wp[3];
            o[0] = fma2(q0.x, v, o[0]); o[1] = fma2(q0.y, v, o[1]);
            o[2] = fma2(q1.x, v, o[2]); o[3] = fma2(q1.y, v, o[3]);
            o[4] = fma2(q2.x, v, o[4]); o[5] = fma2(q2.y, v, o[5]);
            o[6] = fma2(q3.x, v, o[6]); o[7] = fma2(q3.y, v, o[7]);
        }
        {
            u64 v = splat2(hi);
            const ulonglong2* wp = (const ulonglong2*)&sm->shw[2 * k + 1][0];
            ulonglong2 q0 = wp[0], q1 = wp[1], q2 = wp[2], q3 = wp[3];
            o[0] = fma2(q0.x, v, o[0]); o[1] = fma2(q0.y, v, o[1]);
            o[2] = fma2(q1.x, v, o[2]); o[3] = fma2(q1.y, v, o[3]);
            o[4] = fma2(q2.x, v, o[4]); o[5] = fma2(q2.y, v, o[5]);
            o[6] = fma2(q3.x, v, o[6]); o[7] = fma2(q3.y, v, o[7]);
        }
    }
}

// ---------------- fused per-layer kernel: 1 node per 64-thread block --------
// launch_bounds(64,12): 85 regs/thread available -> no spills (the R13-R15
// 64-reg cap was forcing LDL/STL spill traffic through L1)
__global__ void __launch_bounds__(64, 12) k_layer(
    const float* __restrict__ xe_rows, int use_psrc,
    float* __restrict__ xe_out, const int* __restrict__ qend,
    const float* __restrict__ b1, const float* __restrict__ w2,
    const float* __restrict__ b2,
    const float* __restrict__ g1, const float* __restrict__ be1,
    const float* __restrict__ g2, const float* __restrict__ be2) {
    __shared__ NodeSm smx;
    NodeSm* sm = &smx;
    int t = blockIdx.x;
    int u = threadIdx.x;          // 0..63; lanes u and u+64

    if (t >= 1600) {   // const-edge writers (layer-0 grid only)
        int i = t - 1600;
        int n = (i < 200) ? i : (1600 + i);
        float xb0 = g_xT[n * Bb + u], xb1 = g_xT[n * Bb + u + 64];
        int qs = g_rsS[n], qe = g_sb2[n];
        for (int q = qs; q < qe; q++) {
            float bb = g_pb3[q];
            g_xeA[q * Bb + u]      = xb0 + bb;
            g_xeA[q * Bb + u + 64] = xb1 + bb;
            g_xeB[q * Bb + u]      = xb0 + bb;
            g_xeB[q * Bb + u + 64] = xb1 + bb;
        }
        return;
    }

    int n = 200 + t;
    const int* rowix = use_psrc ? g_psrcd : g_rowidx;

    // w2 tile prefetch (visibility via first gather barrier)
    {
        const float4* w2p = (const float4*)(w2 + n * 256);
        ((float4*)sm->shw)[u] = w2p[u];
    }

    int rs = g_rsD[n], re = g_rsD[n + 1];

    u64 a0[8], a1[8];
    {
        const ulonglong2* bp = (const ulonglong2*)(b1 + n * 16);
#pragma unroll
        for (int k = 0; k < 4; k++) {
            ulonglong2 q = bp[k];
            a0[2 * k] = q.x; a0[2 * k + 1] = q.y;
            a1[2 * k] = q.x; a1[2 * k + 1] = q.y;
        }
    }

    // ---- gather ----
    for (int cbase = rs; cbase < re; cbase += CH) {
        int cnt = min(CH, re - cbase);
        __syncthreads();
        for (int i = u; i < cnt * 16; i += 64) sm->stage[i] = g_pw1[cbase * 16 + i];
        if (u < cnt) sm->sidx[u] = rowix[cbase + u];
        __syncthreads();
        for (int jb = 0; jb < cnt; jb += 4) {
            float x0[4], x1[4];
#pragma unroll
            for (int j = 0; j < 4; j++) {
                int jj = jb + j;
                if (jj < cnt) {
                    int r = sm->sidx[jj];
                    x0[j] = xe_rows[r + u];
                    x1[j] = xe_rows[r + u + 64];
                } else { x0[j] = 0.f; x1[j] = 0.f; }
            }
#pragma unroll
            for (int j = 0; j < 4; j++) {
                int jj = jb + j;
                if (jj < cnt) {
                    u64 v0 = splat2(x0[j]), v1 = splat2(x1[j]);
                    const ulonglong2* wp = (const ulonglong2*)&sm->stage[jj * 16];
                    ulonglong2 q0 = wp[0], q1 = wp[1], q2 = wp[2], q3 = wp[3];
                    a0[0] = fma2(q0.x, v0, a0[0]); a0[1] = fma2(q0.y, v0, a0[1]);
                    a0[2] = fma2(q1.x, v0, a0[2]); a0[3] = fma2(q1.y, v0, a0[3]);
                    a0[4] = fma2(q2.x, v0, a0[4]); a0[5] = fma2(q2.y, v0, a0[5]);
                    a0[6] = fma2(q3.x, v0, a0[6]); a0[7] = fma2(q3.y, v0, a0[7]);
                    a1[0] = fma2(q0.x, v1, a1[0]); a1[1] = fma2(q0.y, v1, a1[1]);
                    a1[2] = fma2(q1.x, v1, a1[2]); a1[3] = fma2(q1.y, v1, a1[3]);
                    a1[4] = fma2(q2.x, v1, a1[4]); a1[5] = fma2(q2.y, v1, a1[5]);
                    a1[6] = fma2(q3.x, v1, a1[6]); a1[7] = fma2(q3.y, v1, a1[7]);
                }
            }
        }
    }

    bn_elu2(a0, a1, n, u, g1, be1, sm);

    // ---- 16x16 matmul straight from registers ----
    u64 o0[8];
    {
        const ulonglong2* bp = (const ulonglong2*)(b2 + n * 16);
#pragma unroll
        for (int k = 0; k < 4; k++) {
            ulonglong2 q = bp[k];
            o0[2 * k] = q.x; o0[2 * k + 1] = q.y;
        }
    }
    mm_lane(o0, a0, sm);     // a0 dies here
    u64 o1[8];
    {
        const ulonglong2* bp = (const ulonglong2*)(b2 + n * 16);
#pragma unroll
        for (int k = 0; k < 4; k++) {
            ulonglong2 q = bp[k];
            o1[2 * k] = q.x; o1[2 * k + 1] = q.y;
        }
    }
    mm_lane(o1, a1, sm);     // a1 dies here

    bn_elu2(o0, o1, n, u, g2, be2, sm);

    // ---- scatter (live edges only) ----
    float xb0 = g_xT[n * Bb + u], xb1 = g_xT[n * Bb + u + 64];
    int qs = g_rsS[n], qe = qend[n];
    for (int cbase = qs; cbase < qe; cbase += CH) {
        int cnt = min(CH, qe - cbase);
        __syncthreads();
        for (int i = u; i < cnt * 16; i += 64) sm->stage[i] = g_pw3m[cbase * 16 + i];
        if (u < cnt) sm->sb3[u] = g_pb3[cbase + u];
        __syncthreads();
        for (int j = 0; j < cnt; j++) {
            const ulonglong2* wq = (const ulonglong2*)&sm->stage[j * 16];
            ulonglong2 q0 = wq[0], q1 = wq[1], q2 = wq[2], q3 = wq[3];
            u64 s0 = 0ULL, s1 = 0ULL;
            s0 = fma2(q0.x, o0[0], s0); s0 = fma2(q0.y, o0[1], s0);
            s0 = fma2(q1.x, o0[2], s0); s0 = fma2(q1.y, o0[3], s0);
            s0 = fma2(q2.x, o0[4], s0); s0 = fma2(q2.y, o0[5], s0);
            s0 = fma2(q3.x, o0[6], s0); s0 = fma2(q3.y, o0[7], s0);
            s1 = fma2(q0.x, o1[0], s1); s1 = fma2(q0.y, o1[1], s1);
            s1 = fma2(q1.x, o1[2], s1); s1 = fma2(q1.y, o1[3], s1);
            s1 = fma2(q2.x, o1[4], s1); s1 = fma2(q2.y, o1[5], s1);
            s1 = fma2(q3.x, o1[6], s1); s1 = fma2(q3.y, o1[7], s1);
            float p, q;
            unpack2(s0, p, q);
            float d0 = p + q;
            unpack2(s1, p, q);
            float d1 = p + q;
            float bb = sm->sb3[j];
            xe_out[(cbase + j) * Bb + u]      = xb0 + bb + d0;
            xe_out[(cbase + j) * Bb + u + 64] = xb1 + bb + d1;
        }
    }
}

// ---------------- final: compact sums, then coalesced output -----------------
__global__ void __launch_bounds__(128) k_sum(const float* __restrict__ xe) {
    int n = 1800 + blockIdx.x;
    int b = threadIdx.x;
    float s = 0.f;
    int rs = g_rsD[n], re = g_rsD[n + 1];
    for (int p = rs; p < re; p++) s += xe[g_rowidx[p] + b];
    g_osum[blockIdx.x * Bb + b] = s;
}

__global__ void __launch_bounds__(256) k_out(float* __restrict__ out) {
    int t = blockIdx.x * 256 + threadIdx.x;
    if (t < Bb * Nn) {
        int n = t % Nn;
        int b = t / Nn;
        out[t] = (n >= 1800) ? g_osum[(n - 1800) * Bb + b] : 0.0f;
    }
    if (t < Nn) { g_cntD[t] = 0; g_cntS[t] = 0; g_cntO[t] = 0; g_cntM[t] = 0; }
}

// ---------------- launch ----------------------------------------------------
extern "C" void kernel_launch(void* const* d_in, const int* in_sizes, int n_in,
                              void* d_out, int out_size) {
    const float* x   = (const float*)d_in[0];
    const float* w1  = (const float*)d_in[1];
    const float* b1  = (const float*)d_in[2];
    const float* w2  = (const float*)d_in[3];
    const float* b2  = (const float*)d_in[4];
    const float* w3  = (const float*)d_in[5];
    const float* b3  = (const float*)d_in[6];
    const float* g1  = (const float*)d_in[7];
    const float* be1 = (const float*)d_in[8];
    const float* g2  = (const float*)d_in[9];
    const float* be2 = (const float*)d_in[10];
    const int*   ei  = (const int*)d_in[11];
    float* out = (float*)d_out;

    const int* src = ei;
    const int* dst = ei + Ee;

    static float* xeA = nullptr;
    static float* xeB = nullptr;
    static float* xT  = nullptr;
    static int*   sb1 = nullptr;
    static int*   sb2 = nullptr;
    if (!xeA) {
        cudaGetSymbolAddress((void**)&xeA, g_xeA);
        cudaGetSymbolAddress((void**)&xeB, g_xeB);
        cudaGetSymbolAddress((void**)&xT,  g_xT);
        cudaGetSymbolAddress((void**)&sb1, g_sb1);
        cudaGetSymbolAddress((void**)&sb2, g_sb2);
        cudaFuncSetAttribute(k_layer,
            cudaFuncAttributePreferredSharedMemoryCarveout, 100);
    }

    dim3 gInit(63, 4);
    k_init<<<gInit, 256>>>(x, src, dst);
    k_scan<<<2, 1024>>>();
    k_build<<<(Ee + 127) / 128, 128>>>(w1, w3, b3, src, dst);

    k_layer<<<2000, 64>>>(xT,  1, xeA, sb2, b1, w2, b2, g1, be1, g2, be2);
    k_layer<<<1600, 64>>>(xeA, 0, xeB, sb2, b1, w2, b2, g1, be1, g2, be2);
    k_layer<<<1600, 64>>>(xeB, 0, xeA, sb2, b1, w2, b2, g1, be1, g2, be2);
    k_layer<<<1600, 64>>>(xeA, 0, xeB, sb1, b1, w2, b2, g1, be1, g2, be2);

    k_sum<<<200, 128>>>(xeB);
    k_out<<<(Bb * Nn + 255) / 256, 256>>>(out);
}